// round 11
// baseline (speedup 1.0000x reference)
#include <cuda_runtime.h>
#include <cuda_bf16.h>
#include <cstdint>
#include <math.h>
#include <math_constants.h>

typedef unsigned int u32;

// Problem constants
#define BATCH 2
#define SEQ   2048
#define DMODEL 2048
#define NHEAD 16
#define HDIM  128
#define ROWS  (BATCH * SEQ)          // 4096
#define QKV_N (3 * DMODEL)           // 6144

// Scratch (allocation-free rule: __device__ globals)
__device__ float g_qkv[(size_t)ROWS * QKV_N];      // [4096, 6144]
__device__ float g_att[(size_t)ROWS * DMODEL];     // [4096, 2048] (tf32-rounded)
__device__ float g_xr[(size_t)ROWS * DMODEL];      // tf32-rounded x
__device__ float g_wqkvr[(size_t)DMODEL * QKV_N];  // tf32-rounded Wqkv
__device__ float g_wprojr[(size_t)DMODEL * DMODEL];// tf32-rounded Wproj

// ---------------------------------------------------------------------------
// Helpers
// ---------------------------------------------------------------------------
__device__ __forceinline__ u32 f2tf32(float x) {
    u32 r;
    asm("cvt.rna.tf32.f32 %0, %1;" : "=r"(r) : "f"(x));
    return r;
}
__device__ __forceinline__ float tf32f(float x) {
    return __uint_as_float(f2tf32(x));
}

__device__ __forceinline__ void cp_async16(u32 smem_addr, const void* gptr) {
    asm volatile("cp.async.cg.shared.global [%0], [%1], 16;\n"
                 :: "r"(smem_addr), "l"(gptr));
}
__device__ __forceinline__ void cp_commit() {
    asm volatile("cp.async.commit_group;\n" ::: "memory");
}
template <int N>
__device__ __forceinline__ void cp_wait() {
    asm volatile("cp.async.wait_group %0;\n" :: "n"(N) : "memory");
}

__device__ __forceinline__ void mma_tf32(float* c, const u32* a, const u32* b) {
    asm volatile(
        "mma.sync.aligned.m16n8k8.row.col.f32.tf32.tf32.f32 "
        "{%0,%1,%2,%3}, {%4,%5,%6,%7}, {%8,%9}, {%0,%1,%2,%3};\n"
        : "+f"(c[0]), "+f"(c[1]), "+f"(c[2]), "+f"(c[3])
        : "r"(a[0]), "r"(a[1]), "r"(a[2]), "r"(a[3]), "r"(b[0]), "r"(b[1]));
}

// ---------------------------------------------------------------------------
// Elementwise tf32 pre-round (hoists cvt out of GEMM inner loops)
// ---------------------------------------------------------------------------
__global__ __launch_bounds__(256)
void round_tf32(const float* __restrict__ in, float* __restrict__ out, int n4) {
    int i = blockIdx.x * 256 + threadIdx.x;
    if (i < n4) {
        float4 v = ((const float4*)in)[i];
        v.x = tf32f(v.x); v.y = tf32f(v.y); v.z = tf32f(v.z); v.w = tf32f(v.w);
        ((float4*)out)[i] = v;
    }
}

// ---------------------------------------------------------------------------
// TF32 tensor-core GEMM: C[M,N] = A[M,K] @ B[K,N] + bias[N]
// A and B MUST be pre-rounded to tf32. 128x128 tile, BK=16, 3-stage cp.async,
// 8 warps, warp tile 32x64, plain bit-loads on the fragment path.
// ---------------------------------------------------------------------------
#define GBM 128
#define GBN 128
#define GBK 16
#define ASTR 20
#define BSTR 136
#define NSTAGE 3
#define A_TILE_F (GBM * ASTR)      // 2560 floats
#define B_TILE_F (GBK * BSTR)      // 2176 floats
#define GEMM_SMEM_BYTES ((NSTAGE * (A_TILE_F + B_TILE_F)) * 4)  // 56832

__global__ __launch_bounds__(256, 2)
void gemm_tf32(const float* __restrict__ A, const float* __restrict__ B,
               const float* __restrict__ bias, float* __restrict__ C,
               int M, int N, int K) {
    extern __shared__ float smg[];
    float* Asm = smg;                          // [NSTAGE][A_TILE_F]
    float* Bsm = smg + NSTAGE * A_TILE_F;      // [NSTAGE][B_TILE_F]

    const int tid = threadIdx.x;
    const int lane = tid & 31;
    const int wid  = tid >> 5;
    const int g = lane >> 2;
    const int t = lane & 3;
    const int warp_m = (wid & 3) * 32;
    const int warp_n = (wid >> 2) * 64;

    const int rowBase = blockIdx.y * GBM;
    const int colBase = blockIdx.x * GBN;

    u32 asbase = (u32)__cvta_generic_to_shared(Asm);
    u32 bsbase = (u32)__cvta_generic_to_shared(Bsm);

    float acc[2][8][4];
    #pragma unroll
    for (int i = 0; i < 2; i++)
        #pragma unroll
        for (int j = 0; j < 8; j++)
            #pragma unroll
            for (int v = 0; v < 4; v++) acc[i][j][v] = 0.0f;

    const int NT = K / GBK;

    // Prologue: issue tiles 0 and 1 (one commit-group per tile)
    #pragma unroll
    for (int s = 0; s < NSTAGE - 1; s++) {
        const int k0g = s * GBK;
        u32 asd = asbase + (u32)s * (A_TILE_F * 4u);
        u32 bsd = bsbase + (u32)s * (B_TILE_F * 4u);
        #pragma unroll
        for (int it = 0; it < 2; it++) {
            int c = tid + it * 256;
            int ar = c >> 2, akc = (c & 3) * 4;
            cp_async16(asd + (u32)(ar * ASTR + akc) * 4u,
                       &A[(size_t)(rowBase + ar) * K + k0g + akc]);
            int br = c >> 5, bnc = (c & 31) * 4;
            cp_async16(bsd + (u32)(br * BSTR + bnc) * 4u,
                       &B[(size_t)(k0g + br) * N + colBase + bnc]);
        }
        cp_commit();
    }

    for (int kt = 0; kt < NT; kt++) {
        // Issue tile kt+2 (possibly empty group, keeps group count uniform)
        if (kt + NSTAGE - 1 < NT) {
            const int s = (kt + NSTAGE - 1) % NSTAGE;
            const int k0g = (kt + NSTAGE - 1) * GBK;
            u32 asd = asbase + (u32)s * (A_TILE_F * 4u);
            u32 bsd = bsbase + (u32)s * (B_TILE_F * 4u);
            #pragma unroll
            for (int it = 0; it < 2; it++) {
                int c = tid + it * 256;
                int ar = c >> 2, akc = (c & 3) * 4;
                cp_async16(asd + (u32)(ar * ASTR + akc) * 4u,
                           &A[(size_t)(rowBase + ar) * K + k0g + akc]);
                int br = c >> 5, bnc = (c & 31) * 4;
                cp_async16(bsd + (u32)(br * BSTR + bnc) * 4u,
                           &B[(size_t)(k0g + br) * N + colBase + bnc]);
            }
        }
        cp_commit();
        cp_wait<NSTAGE - 1>();   // tile kt's group complete
        __syncthreads();

        const int buf = kt % NSTAGE;
        const u32* Au = (const u32*)(Asm + buf * A_TILE_F);
        const u32* Bu = (const u32*)(Bsm + buf * B_TILE_F);
        #pragma unroll
        for (int ks = 0; ks < 2; ks++) {
            const int k0 = ks * 8;
            u32 af[2][4];
            u32 bf[8][2];
            #pragma unroll
            for (int mt = 0; mt < 2; mt++) {
                int m = warp_m + mt * 16 + g;
                af[mt][0] = Au[m * ASTR + k0 + t];
                af[mt][1] = Au[(m + 8) * ASTR + k0 + t];
                af[mt][2] = Au[m * ASTR + k0 + t + 4];
                af[mt][3] = Au[(m + 8) * ASTR + k0 + t + 4];
            }
            #pragma unroll
            for (int nt = 0; nt < 8; nt++) {
                int n = warp_n + nt * 8 + g;
                bf[nt][0] = Bu[(k0 + t) * BSTR + n];
                bf[nt][1] = Bu[(k0 + t + 4) * BSTR + n];
            }
            #pragma unroll
            for (int mt = 0; mt < 2; mt++)
                #pragma unroll
                for (int nt = 0; nt < 8; nt++)
                    mma_tf32(acc[mt][nt], af[mt], bf[nt]);
        }
        __syncthreads();
    }

    #pragma unroll
    for (int mt = 0; mt < 2; mt++) {
        int row = rowBase + warp_m + mt * 16 + g;
        #pragma unroll
        for (int nt = 0; nt < 8; nt++) {
            int col = colBase + warp_n + nt * 8 + 2 * t;
            float b0 = bias[col], b1 = bias[col + 1];
            float2 v0 = make_float2(acc[mt][nt][0] + b0, acc[mt][nt][1] + b1);
            float2 v1 = make_float2(acc[mt][nt][2] + b0, acc[mt][nt][3] + b1);
            *(float2*)&C[(size_t)row * N + col] = v0;
            *(float2*)&C[(size_t)(row + 8) * N + col] = v1;
        }
    }
}

// ---------------------------------------------------------------------------
// Flash attention with tf32 tensor-core mma for QK^T and P@V.
// (unchanged from Round 10 except: epilogue writes tf32-rounded output, so the
//  proj GEMM can consume it with plain bit-loads — numerically identical to
//  the old frag-load rounding.)
// ---------------------------------------------------------------------------
#define QT 64
#define QPAD 132
#define SPAD 68
#define AQ_FLOATS (QT * QPAD)
#define AS_FLOATS (QT * SPAD)
#define ATTN_SMEM_FLOATS (3 * AQ_FLOATS + AS_FLOATS + 2 * 128)
#define ATTN_SMEM_BYTES  (ATTN_SMEM_FLOATS * 4)

__global__ __launch_bounds__(256, 1)
void attn_mma(const float* __restrict__ qkv, float* __restrict__ out) {
    extern __shared__ float sm[];
    float* Qs   = sm;
    float* Ks   = Qs + AQ_FLOATS;
    float* Vs   = Ks + AQ_FLOATS;
    float* Ss   = Vs + AQ_FLOATS;
    float* pmax = Ss + AS_FLOATS;
    float* psum = pmax + 128;

    const int qt  = gridDim.x - 1 - blockIdx.x;
    const int h   = blockIdx.y;
    const int b   = blockIdx.z;
    const int tid = threadIdx.x;
    const int lane = tid & 31;
    const int w    = tid >> 5;
    const int g    = lane >> 2;
    const int t    = lane & 3;
    const int wm   = (w & 3) * 16;
    const int wh   = w >> 2;
    const int wn   = wh * 32;
    const int wd   = wh * 64;

    const float scale = 0.08838834764831845f;
    const size_t base = (size_t)b * SEQ * QKV_N;
    const int hoff = h * HDIM;

    for (int idx = tid; idx < QT * 32; idx += 256) {
        int r  = idx >> 5;
        int d4 = (idx & 31) * 4;
        float4 v = *(const float4*)&qkv[base + (size_t)(qt * QT + r) * QKV_N + hoff + d4];
        Qs[r * QPAD + d4 + 0] = tf32f(v.x * scale);
        Qs[r * QPAD + d4 + 1] = tf32f(v.y * scale);
        Qs[r * QPAD + d4 + 2] = tf32f(v.z * scale);
        Qs[r * QPAD + d4 + 3] = tf32f(v.w * scale);
    }

    float m_run[2] = { -CUDART_INF_F, -CUDART_INF_F };
    float l_run[2] = { 0.0f, 0.0f };
    float O[8][4];
    #pragma unroll
    for (int dbl = 0; dbl < 8; dbl++)
        #pragma unroll
        for (int v = 0; v < 4; v++) O[dbl][v] = 0.0f;

    for (int kt = 0; kt <= qt; kt++) {
        __syncthreads();
        for (int idx = tid; idx < QT * 32; idx += 256) {
            int r  = idx >> 5;
            int d4 = (idx & 31) * 4;
            size_t rowoff = base + (size_t)(kt * QT + r) * QKV_N + hoff;
            float4 kv = *(const float4*)&qkv[rowoff + DMODEL + d4];
            float4 vv = *(const float4*)&qkv[rowoff + 2 * DMODEL + d4];
            Ks[r * QPAD + d4 + 0] = tf32f(kv.x);
            Ks[r * QPAD + d4 + 1] = tf32f(kv.y);
            Ks[r * QPAD + d4 + 2] = tf32f(kv.z);
            Ks[r * QPAD + d4 + 3] = tf32f(kv.w);
            Vs[r * QPAD + d4 + 0] = tf32f(vv.x);
            Vs[r * QPAD + d4 + 1] = tf32f(vv.y);
            Vs[r * QPAD + d4 + 2] = tf32f(vv.z);
            Vs[r * QPAD + d4 + 3] = tf32f(vv.w);
        }
        __syncthreads();

        float sa[4][4];
        #pragma unroll
        for (int nb = 0; nb < 4; nb++)
            #pragma unroll
            for (int v = 0; v < 4; v++) sa[nb][v] = 0.0f;

        #pragma unroll
        for (int ks = 0; ks < 16; ks++) {
            const int k0 = ks * 8;
            u32 A[4];
            A[0] = __float_as_uint(Qs[(wm + g) * QPAD + k0 + t]);
            A[1] = __float_as_uint(Qs[(wm + 8 + g) * QPAD + k0 + t]);
            A[2] = __float_as_uint(Qs[(wm + g) * QPAD + k0 + t + 4]);
            A[3] = __float_as_uint(Qs[(wm + 8 + g) * QPAD + k0 + t + 4]);
            #pragma unroll
            for (int nb = 0; nb < 4; nb++) {
                const int n0 = wn + nb * 8;
                u32 Bq[2];
                Bq[0] = __float_as_uint(Ks[(n0 + g) * QPAD + k0 + t]);
                Bq[1] = __float_as_uint(Ks[(n0 + g) * QPAD + k0 + t + 4]);
                mma_tf32(sa[nb], A, Bq);
            }
        }

        if (kt == qt) {
            #pragma unroll
            for (int nb = 0; nb < 4; nb++) {
                const int c0 = wn + nb * 8 + 2 * t;
                if (c0     > wm + g)     sa[nb][0] = -CUDART_INF_F;
                if (c0 + 1 > wm + g)     sa[nb][1] = -CUDART_INF_F;
                if (c0     > wm + 8 + g) sa[nb][2] = -CUDART_INF_F;
                if (c0 + 1 > wm + 8 + g) sa[nb][3] = -CUDART_INF_F;
            }
        }

        float tmax[2];
        tmax[0] = fmaxf(fmaxf(sa[0][0], sa[0][1]), fmaxf(sa[1][0], sa[1][1]));
        tmax[0] = fmaxf(tmax[0], fmaxf(fmaxf(sa[2][0], sa[2][1]), fmaxf(sa[3][0], sa[3][1])));
        tmax[1] = fmaxf(fmaxf(sa[0][2], sa[0][3]), fmaxf(sa[1][2], sa[1][3]));
        tmax[1] = fmaxf(tmax[1], fmaxf(fmaxf(sa[2][2], sa[2][3]), fmaxf(sa[3][2], sa[3][3])));
        #pragma unroll
        for (int i = 0; i < 2; i++) {
            tmax[i] = fmaxf(tmax[i], __shfl_xor_sync(0xffffffffu, tmax[i], 1));
            tmax[i] = fmaxf(tmax[i], __shfl_xor_sync(0xffffffffu, tmax[i], 2));
        }
        if (t == 0) {
            pmax[(wm + g) * 2 + wh]     = tmax[0];
            pmax[(wm + 8 + g) * 2 + wh] = tmax[1];
        }
        __syncthreads();

        float fs[2];
        #pragma unroll
        for (int i = 0; i < 2; i++) {
            const int r = wm + g + 8 * i;
            float mt2 = fmaxf(pmax[r * 2 + 0], pmax[r * 2 + 1]);
            float mn = fmaxf(m_run[i], mt2);
            fs[i] = __expf(m_run[i] - mn);
            m_run[i] = mn;
        }

        float tsum[2] = { 0.0f, 0.0f };
        #pragma unroll
        for (int nb = 0; nb < 4; nb++) {
            float p0 = tf32f(__expf(sa[nb][0] - m_run[0]));
            float p1 = tf32f(__expf(sa[nb][1] - m_run[0]));
            float p2 = tf32f(__expf(sa[nb][2] - m_run[1]));
            float p3 = tf32f(__expf(sa[nb][3] - m_run[1]));
            tsum[0] += p0 + p1;
            tsum[1] += p2 + p3;
            const int col = wn + nb * 8 + 2 * t;
            *(float2*)&Ss[(wm + g) * SPAD + col]     = make_float2(p0, p1);
            *(float2*)&Ss[(wm + 8 + g) * SPAD + col] = make_float2(p2, p3);
        }
        #pragma unroll
        for (int i = 0; i < 2; i++) {
            tsum[i] += __shfl_xor_sync(0xffffffffu, tsum[i], 1);
            tsum[i] += __shfl_xor_sync(0xffffffffu, tsum[i], 2);
        }
        if (t == 0) {
            psum[(wm + g) * 2 + wh]     = tsum[0];
            psum[(wm + 8 + g) * 2 + wh] = tsum[1];
        }
        __syncthreads();

        #pragma unroll
        for (int i = 0; i < 2; i++) {
            const int r = wm + g + 8 * i;
            l_run[i] = l_run[i] * fs[i] + psum[r * 2 + 0] + psum[r * 2 + 1];
        }

        #pragma unroll
        for (int dbl = 0; dbl < 8; dbl++) {
            O[dbl][0] *= fs[0];
            O[dbl][1] *= fs[0];
            O[dbl][2] *= fs[1];
            O[dbl][3] *= fs[1];
        }
        #pragma unroll
        for (int ks = 0; ks < 8; ks++) {
            const int k0 = ks * 8;
            u32 A[4];
            A[0] = __float_as_uint(Ss[(wm + g) * SPAD + k0 + t]);
            A[1] = __float_as_uint(Ss[(wm + 8 + g) * SPAD + k0 + t]);
            A[2] = __float_as_uint(Ss[(wm + g) * SPAD + k0 + t + 4]);
            A[3] = __float_as_uint(Ss[(wm + 8 + g) * SPAD + k0 + t + 4]);
            #pragma unroll
            for (int dbl = 0; dbl < 8; dbl++) {
                const int d0 = wd + dbl * 8;
                u32 Bv[2];
                Bv[0] = __float_as_uint(Vs[(k0 + t) * QPAD + d0 + g]);
                Bv[1] = __float_as_uint(Vs[(k0 + t + 4) * QPAD + d0 + g]);
                mma_tf32(O[dbl], A, Bv);
            }
        }
    }

    // Epilogue: O /= l, tf32-rounded for the proj GEMM's plain-load A path
    float inv0 = 1.0f / l_run[0];
    float inv1 = 1.0f / l_run[1];
    const size_t obase = ((size_t)b * SEQ + (size_t)qt * QT) * DMODEL + hoff;
    #pragma unroll
    for (int dbl = 0; dbl < 8; dbl++) {
        const int col = wd + dbl * 8 + 2 * t;
        float2 v0 = make_float2(tf32f(O[dbl][0] * inv0), tf32f(O[dbl][1] * inv0));
        float2 v1 = make_float2(tf32f(O[dbl][2] * inv1), tf32f(O[dbl][3] * inv1));
        *(float2*)&out[obase + (size_t)(wm + g) * DMODEL + col] = v0;
        *(float2*)&out[obase + (size_t)(wm + 8 + g) * DMODEL + col] = v1;
    }
}

// ---------------------------------------------------------------------------
// Launch
// ---------------------------------------------------------------------------
extern "C" void kernel_launch(void* const* d_in, const int* in_sizes, int n_in,
                              void* d_out, int out_size) {
    const float* x     = (const float*)d_in[0];
    const float* Wqkv  = (const float*)d_in[1];
    const float* bqkv  = (const float*)d_in[2];
    const float* Wproj = (const float*)d_in[3];
    const float* bproj = (const float*)d_in[4];
    float* out = (float*)d_out;

    float *qkv, *att, *xr, *wqkvr, *wprojr;
    cudaGetSymbolAddress((void**)&qkv, g_qkv);
    cudaGetSymbolAddress((void**)&att, g_att);
    cudaGetSymbolAddress((void**)&xr, g_xr);
    cudaGetSymbolAddress((void**)&wqkvr, g_wqkvr);
    cudaGetSymbolAddress((void**)&wprojr, g_wprojr);

    cudaFuncSetAttribute(attn_mma, cudaFuncAttributeMaxDynamicSharedMemorySize,
                         ATTN_SMEM_BYTES);
    cudaFuncSetAttribute(gemm_tf32, cudaFuncAttributeMaxDynamicSharedMemorySize,
                         GEMM_SMEM_BYTES);

    // 0) Pre-round inputs to tf32 (one-time per launch, ~40us)
    {
        int n4x = ROWS * DMODEL / 4;
        int n4q = DMODEL * QKV_N / 4;
        int n4p = DMODEL * DMODEL / 4;
        round_tf32<<<(n4x + 255) / 256, 256>>>(x, xr, n4x);
        round_tf32<<<(n4q + 255) / 256, 256>>>(Wqkv, wqkvr, n4q);
        round_tf32<<<(n4p + 255) / 256, 256>>>(Wproj, wprojr, n4p);
    }
    // 1) QKV GEMM: [4096,2048] @ [2048,6144] + bqkv
    {
        dim3 grid(QKV_N / GBN, ROWS / GBM);
        gemm_tf32<<<grid, 256, GEMM_SMEM_BYTES>>>(xr, wqkvr, bqkv, qkv,
                                                  ROWS, QKV_N, DMODEL);
    }
    // 2) Causal attention (tf32 mma)
    {
        dim3 grid(SEQ / QT, NHEAD, BATCH);
        attn_mma<<<grid, 256, ATTN_SMEM_BYTES>>>(qkv, att);
    }
    // 3) Proj GEMM: [4096,2048] @ [2048,2048] + bproj
    {
        dim3 grid(DMODEL / GBN, ROWS / GBM);
        gemm_tf32<<<grid, 256, GEMM_SMEM_BYTES>>>(att, wprojr, bproj, out,
                                                  ROWS, DMODEL, DMODEL);
    }
}

// round 12
// speedup vs baseline: 1.5844x; 1.5844x over previous
#include <cuda_runtime.h>
#include <cuda_fp16.h>
#include <cstdint>
#include <math.h>
#include <math_constants.h>

typedef unsigned int u32;

// Problem constants
#define BATCH 2
#define SEQ   2048
#define DMODEL 2048
#define NHEAD 16
#define HDIM  128
#define ROWS  (BATCH * SEQ)          // 4096
#define QKV_N (3 * DMODEL)           // 6144

// Scratch (allocation-free rule: __device__ globals)
__device__ float  g_qkv[(size_t)ROWS * QKV_N];       // fp32 QKV activations
__device__ __half g_atth[(size_t)ROWS * DMODEL];     // fp16 attention output
__device__ __half g_xh[(size_t)ROWS * DMODEL];       // fp16 x
__device__ __half g_wqkvh[(size_t)DMODEL * QKV_N];   // fp16 Wqkv
__device__ __half g_wprojh[(size_t)DMODEL * DMODEL]; // fp16 Wproj

// ---------------------------------------------------------------------------
// Helpers
// ---------------------------------------------------------------------------
__device__ __forceinline__ u32 f2tf32(float x) {
    u32 r;
    asm("cvt.rna.tf32.f32 %0, %1;" : "=r"(r) : "f"(x));
    return r;
}
__device__ __forceinline__ float tf32f(float x) {
    return __uint_as_float(f2tf32(x));
}

__device__ __forceinline__ void cp_async16(u32 smem_addr, const void* gptr) {
    asm volatile("cp.async.cg.shared.global [%0], [%1], 16;\n"
                 :: "r"(smem_addr), "l"(gptr));
}
__device__ __forceinline__ void cp_commit() {
    asm volatile("cp.async.commit_group;\n" ::: "memory");
}
template <int N>
__device__ __forceinline__ void cp_wait() {
    asm volatile("cp.async.wait_group %0;\n" :: "n"(N) : "memory");
}

__device__ __forceinline__ void mma_tf32(float* c, const u32* a, const u32* b) {
    asm volatile(
        "mma.sync.aligned.m16n8k8.row.col.f32.tf32.tf32.f32 "
        "{%0,%1,%2,%3}, {%4,%5,%6,%7}, {%8,%9}, {%0,%1,%2,%3};\n"
        : "+f"(c[0]), "+f"(c[1]), "+f"(c[2]), "+f"(c[3])
        : "r"(a[0]), "r"(a[1]), "r"(a[2]), "r"(a[3]), "r"(b[0]), "r"(b[1]));
}

__device__ __forceinline__ void mma_f16(float* c, const u32* a, const u32* b) {
    asm volatile(
        "mma.sync.aligned.m16n8k16.row.col.f32.f16.f16.f32 "
        "{%0,%1,%2,%3}, {%4,%5,%6,%7}, {%8,%9}, {%0,%1,%2,%3};\n"
        : "+f"(c[0]), "+f"(c[1]), "+f"(c[2]), "+f"(c[3])
        : "r"(a[0]), "r"(a[1]), "r"(a[2]), "r"(a[3]), "r"(b[0]), "r"(b[1]));
}

__device__ __forceinline__ void ldsm_x4(u32* r, u32 addr) {
    asm volatile("ldmatrix.sync.aligned.m8n8.x4.shared.b16 {%0,%1,%2,%3}, [%4];"
                 : "=r"(r[0]), "=r"(r[1]), "=r"(r[2]), "=r"(r[3]) : "r"(addr));
}
__device__ __forceinline__ void ldsm_x4_t(u32* r, u32 addr) {
    asm volatile("ldmatrix.sync.aligned.m8n8.x4.trans.shared.b16 {%0,%1,%2,%3}, [%4];"
                 : "=r"(r[0]), "=r"(r[1]), "=r"(r[2]), "=r"(r[3]) : "r"(addr));
}

// ---------------------------------------------------------------------------
// Elementwise fp32 -> fp16 prepass
// ---------------------------------------------------------------------------
__global__ __launch_bounds__(256)
void to_half(const float* __restrict__ in, __half* __restrict__ out, int n4) {
    int i = blockIdx.x * 256 + threadIdx.x;
    if (i < n4) {
        float4 v = ((const float4*)in)[i];
        __half2* o = (__half2*)out;
        o[2 * i + 0] = __floats2half2_rn(v.x, v.y);
        o[2 * i + 1] = __floats2half2_rn(v.z, v.w);
    }
}

// ---------------------------------------------------------------------------
// FP16 tensor-core GEMM: C[M,N] = A[M,K] @ B[K,N] + bias[N]
// A,B fp16 (pre-converted), C fp32. 128x128 tile, BK=32, 3-stage cp.async,
// 8 warps, warp tile 32x64, ldmatrix fragment loads, m16n8k16 mma.
// SMEM strides: A 40 halves (80B), B 136 halves (272B) -- both give the 8
// LDSM phase rows distinct 16B chunks mod 128B => conflict-free.
// ---------------------------------------------------------------------------
#define GBM 128
#define GBN 128
#define GBK 32
#define HASTR 40          // halves
#define HBSTR 136         // halves
#define NSTAGE 3
#define A_TILE_H (GBM * HASTR)     // 5120 halves = 10240 B
#define B_TILE_H (GBK * HBSTR)     // 4352 halves = 8704 B
#define GEMM_SMEM_BYTES (NSTAGE * (A_TILE_H + B_TILE_H) * 2)   // 56832

__global__ __launch_bounds__(256, 2)
void gemm_f16(const __half* __restrict__ A, const __half* __restrict__ B,
              const float* __restrict__ bias, float* __restrict__ C,
              int M, int N, int K) {
    extern __shared__ __half smh[];
    __half* Asm = smh;
    __half* Bsm = smh + NSTAGE * A_TILE_H;

    const int tid = threadIdx.x;
    const int lane = tid & 31;
    const int wid  = tid >> 5;
    const int g = lane >> 2;
    const int t = lane & 3;
    const int warp_m = (wid & 3) * 32;
    const int warp_n = (wid >> 2) * 64;

    const int rowBase = blockIdx.y * GBM;
    const int colBase = blockIdx.x * GBN;

    u32 asbase = (u32)__cvta_generic_to_shared(Asm);
    u32 bsbase = (u32)__cvta_generic_to_shared(Bsm);

    // ldmatrix per-thread address components
    const int aRow = (lane & 7) + ((lane >> 3) & 1) * 8;  // row within 16-block
    const int aCol = (lane >> 4) * 8;                      // k-half
    const int bRow = (lane & 7) + ((lane >> 3) & 1) * 8;  // k within 16
    const int bColD = (lane >> 4) * 8;                     // n-half within 16

    float acc[2][8][4];
    #pragma unroll
    for (int i = 0; i < 2; i++)
        #pragma unroll
        for (int j = 0; j < 8; j++)
            #pragma unroll
            for (int v = 0; v < 4; v++) acc[i][j][v] = 0.0f;

    const int NT = K / GBK;

    // cp.async mappings (16B = 8 halves per chunk)
    // A tile: 128 rows x 32 halves = 4 chunks/row, 512 chunks
    // B tile: 32 rows x 128 halves = 16 chunks/row, 512 chunks
    // Prologue: tiles 0..NSTAGE-2
    #pragma unroll
    for (int s = 0; s < NSTAGE - 1; s++) {
        const int k0g = s * GBK;
        u32 asd = asbase + (u32)s * (A_TILE_H * 2u);
        u32 bsd = bsbase + (u32)s * (B_TILE_H * 2u);
        #pragma unroll
        for (int it = 0; it < 2; it++) {
            int c = tid + it * 256;
            int ar = c >> 2, akc = (c & 3) * 8;
            cp_async16(asd + (u32)(ar * HASTR + akc) * 2u,
                       &A[(size_t)(rowBase + ar) * K + k0g + akc]);
            int br = c >> 4, bnc = (c & 15) * 8;
            cp_async16(bsd + (u32)(br * HBSTR + bnc) * 2u,
                       &B[(size_t)(k0g + br) * N + colBase + bnc]);
        }
        cp_commit();
    }

    for (int kt = 0; kt < NT; kt++) {
        if (kt + NSTAGE - 1 < NT) {
            const int s = (kt + NSTAGE - 1) % NSTAGE;
            const int k0g = (kt + NSTAGE - 1) * GBK;
            u32 asd = asbase + (u32)s * (A_TILE_H * 2u);
            u32 bsd = bsbase + (u32)s * (B_TILE_H * 2u);
            #pragma unroll
            for (int it = 0; it < 2; it++) {
                int c = tid + it * 256;
                int ar = c >> 2, akc = (c & 3) * 8;
                cp_async16(asd + (u32)(ar * HASTR + akc) * 2u,
                           &A[(size_t)(rowBase + ar) * K + k0g + akc]);
                int br = c >> 4, bnc = (c & 15) * 8;
                cp_async16(bsd + (u32)(br * HBSTR + bnc) * 2u,
                           &B[(size_t)(k0g + br) * N + colBase + bnc]);
            }
        }
        cp_commit();
        cp_wait<NSTAGE - 1>();
        __syncthreads();

        const int buf = kt % NSTAGE;
        const u32 asb = asbase + (u32)buf * (A_TILE_H * 2u);
        const u32 bsb = bsbase + (u32)buf * (B_TILE_H * 2u);

        #pragma unroll
        for (int ks = 0; ks < 2; ks++) {
            const int k0 = ks * 16;
            u32 af[2][4];
            u32 bf[8][2];
            #pragma unroll
            for (int mt = 0; mt < 2; mt++) {
                u32 addr = asb + (u32)((warp_m + mt * 16 + aRow) * HASTR
                                       + k0 + aCol) * 2u;
                ldsm_x4(af[mt], addr);
            }
            #pragma unroll
            for (int nbp = 0; nbp < 4; nbp++) {
                u32 r4[4];
                u32 addr = bsb + (u32)((k0 + bRow) * HBSTR
                                       + warp_n + nbp * 16 + bColD) * 2u;
                ldsm_x4_t(r4, addr);
                bf[nbp * 2 + 0][0] = r4[0]; bf[nbp * 2 + 0][1] = r4[1];
                bf[nbp * 2 + 1][0] = r4[2]; bf[nbp * 2 + 1][1] = r4[3];
            }
            #pragma unroll
            for (int mt = 0; mt < 2; mt++)
                #pragma unroll
                for (int nt = 0; nt < 8; nt++)
                    mma_f16(acc[mt][nt], af[mt], bf[nt]);
        }
        __syncthreads();
    }

    #pragma unroll
    for (int mt = 0; mt < 2; mt++) {
        int row = rowBase + warp_m + mt * 16 + g;
        #pragma unroll
        for (int nt = 0; nt < 8; nt++) {
            int col = colBase + warp_n + nt * 8 + 2 * t;
            float b0 = bias[col], b1 = bias[col + 1];
            float2 v0 = make_float2(acc[mt][nt][0] + b0, acc[mt][nt][1] + b1);
            float2 v1 = make_float2(acc[mt][nt][2] + b0, acc[mt][nt][3] + b1);
            *(float2*)&C[(size_t)row * N + col] = v0;
            *(float2*)&C[(size_t)(row + 8) * N + col] = v1;
        }
    }
}

// ---------------------------------------------------------------------------
// Flash attention with tf32 tensor-core mma (unchanged from Round 10 except
// the epilogue writes fp16 for the proj GEMM -- same mantissa as tf32).
// ---------------------------------------------------------------------------
#define QT 64
#define QPAD 132
#define SPAD 68
#define AQ_FLOATS (QT * QPAD)
#define AS_FLOATS (QT * SPAD)
#define ATTN_SMEM_FLOATS (3 * AQ_FLOATS + AS_FLOATS + 2 * 128)
#define ATTN_SMEM_BYTES  (ATTN_SMEM_FLOATS * 4)

__global__ __launch_bounds__(256, 1)
void attn_mma(const float* __restrict__ qkv, __half* __restrict__ out) {
    extern __shared__ float sm[];
    float* Qs   = sm;
    float* Ks   = Qs + AQ_FLOATS;
    float* Vs   = Ks + AQ_FLOATS;
    float* Ss   = Vs + AQ_FLOATS;
    float* pmax = Ss + AS_FLOATS;
    float* psum = pmax + 128;

    const int qt  = gridDim.x - 1 - blockIdx.x;
    const int h   = blockIdx.y;
    const int b   = blockIdx.z;
    const int tid = threadIdx.x;
    const int lane = tid & 31;
    const int w    = tid >> 5;
    const int g    = lane >> 2;
    const int t    = lane & 3;
    const int wm   = (w & 3) * 16;
    const int wh   = w >> 2;
    const int wn   = wh * 32;
    const int wd   = wh * 64;

    const float scale = 0.08838834764831845f;
    const size_t base = (size_t)b * SEQ * QKV_N;
    const int hoff = h * HDIM;

    for (int idx = tid; idx < QT * 32; idx += 256) {
        int r  = idx >> 5;
        int d4 = (idx & 31) * 4;
        float4 v = *(const float4*)&qkv[base + (size_t)(qt * QT + r) * QKV_N + hoff + d4];
        Qs[r * QPAD + d4 + 0] = tf32f(v.x * scale);
        Qs[r * QPAD + d4 + 1] = tf32f(v.y * scale);
        Qs[r * QPAD + d4 + 2] = tf32f(v.z * scale);
        Qs[r * QPAD + d4 + 3] = tf32f(v.w * scale);
    }

    float m_run[2] = { -CUDART_INF_F, -CUDART_INF_F };
    float l_run[2] = { 0.0f, 0.0f };
    float O[8][4];
    #pragma unroll
    for (int dbl = 0; dbl < 8; dbl++)
        #pragma unroll
        for (int v = 0; v < 4; v++) O[dbl][v] = 0.0f;

    for (int kt = 0; kt <= qt; kt++) {
        __syncthreads();
        for (int idx = tid; idx < QT * 32; idx += 256) {
            int r  = idx >> 5;
            int d4 = (idx & 31) * 4;
            size_t rowoff = base + (size_t)(kt * QT + r) * QKV_N + hoff;
            float4 kv = *(const float4*)&qkv[rowoff + DMODEL + d4];
            float4 vv = *(const float4*)&qkv[rowoff + 2 * DMODEL + d4];
            Ks[r * QPAD + d4 + 0] = tf32f(kv.x);
            Ks[r * QPAD + d4 + 1] = tf32f(kv.y);
            Ks[r * QPAD + d4 + 2] = tf32f(kv.z);
            Ks[r * QPAD + d4 + 3] = tf32f(kv.w);
            Vs[r * QPAD + d4 + 0] = tf32f(vv.x);
            Vs[r * QPAD + d4 + 1] = tf32f(vv.y);
            Vs[r * QPAD + d4 + 2] = tf32f(vv.z);
            Vs[r * QPAD + d4 + 3] = tf32f(vv.w);
        }
        __syncthreads();

        float sa[4][4];
        #pragma unroll
        for (int nb = 0; nb < 4; nb++)
            #pragma unroll
            for (int v = 0; v < 4; v++) sa[nb][v] = 0.0f;

        #pragma unroll
        for (int ks = 0; ks < 16; ks++) {
            const int k0 = ks * 8;
            u32 A[4];
            A[0] = __float_as_uint(Qs[(wm + g) * QPAD + k0 + t]);
            A[1] = __float_as_uint(Qs[(wm + 8 + g) * QPAD + k0 + t]);
            A[2] = __float_as_uint(Qs[(wm + g) * QPAD + k0 + t + 4]);
            A[3] = __float_as_uint(Qs[(wm + 8 + g) * QPAD + k0 + t + 4]);
            #pragma unroll
            for (int nb = 0; nb < 4; nb++) {
                const int n0 = wn + nb * 8;
                u32 Bq[2];
                Bq[0] = __float_as_uint(Ks[(n0 + g) * QPAD + k0 + t]);
                Bq[1] = __float_as_uint(Ks[(n0 + g) * QPAD + k0 + t + 4]);
                mma_tf32(sa[nb], A, Bq);
            }
        }

        if (kt == qt) {
            #pragma unroll
            for (int nb = 0; nb < 4; nb++) {
                const int c0 = wn + nb * 8 + 2 * t;
                if (c0     > wm + g)     sa[nb][0] = -CUDART_INF_F;
                if (c0 + 1 > wm + g)     sa[nb][1] = -CUDART_INF_F;
                if (c0     > wm + 8 + g) sa[nb][2] = -CUDART_INF_F;
                if (c0 + 1 > wm + 8 + g) sa[nb][3] = -CUDART_INF_F;
            }
        }

        float tmax[2];
        tmax[0] = fmaxf(fmaxf(sa[0][0], sa[0][1]), fmaxf(sa[1][0], sa[1][1]));
        tmax[0] = fmaxf(tmax[0], fmaxf(fmaxf(sa[2][0], sa[2][1]), fmaxf(sa[3][0], sa[3][1])));
        tmax[1] = fmaxf(fmaxf(sa[0][2], sa[0][3]), fmaxf(sa[1][2], sa[1][3]));
        tmax[1] = fmaxf(tmax[1], fmaxf(fmaxf(sa[2][2], sa[2][3]), fmaxf(sa[3][2], sa[3][3])));
        #pragma unroll
        for (int i = 0; i < 2; i++) {
            tmax[i] = fmaxf(tmax[i], __shfl_xor_sync(0xffffffffu, tmax[i], 1));
            tmax[i] = fmaxf(tmax[i], __shfl_xor_sync(0xffffffffu, tmax[i], 2));
        }
        if (t == 0) {
            pmax[(wm + g) * 2 + wh]     = tmax[0];
            pmax[(wm + 8 + g) * 2 + wh] = tmax[1];
        }
        __syncthreads();

        float fs[2];
        #pragma unroll
        for (int i = 0; i < 2; i++) {
            const int r = wm + g + 8 * i;
            float mt2 = fmaxf(pmax[r * 2 + 0], pmax[r * 2 + 1]);
            float mn = fmaxf(m_run[i], mt2);
            fs[i] = __expf(m_run[i] - mn);
            m_run[i] = mn;
        }

        float tsum[2] = { 0.0f, 0.0f };
        #pragma unroll
        for (int nb = 0; nb < 4; nb++) {
            float p0 = tf32f(__expf(sa[nb][0] - m_run[0]));
            float p1 = tf32f(__expf(sa[nb][1] - m_run[0]));
            float p2 = tf32f(__expf(sa[nb][2] - m_run[1]));
            float p3 = tf32f(__expf(sa[nb][3] - m_run[1]));
            tsum[0] += p0 + p1;
            tsum[1] += p2 + p3;
            const int col = wn + nb * 8 + 2 * t;
            *(float2*)&Ss[(wm + g) * SPAD + col]     = make_float2(p0, p1);
            *(float2*)&Ss[(wm + 8 + g) * SPAD + col] = make_float2(p2, p3);
        }
        #pragma unroll
        for (int i = 0; i < 2; i++) {
            tsum[i] += __shfl_xor_sync(0xffffffffu, tsum[i], 1);
            tsum[i] += __shfl_xor_sync(0xffffffffu, tsum[i], 2);
        }
        if (t == 0) {
            psum[(wm + g) * 2 + wh]     = tsum[0];
            psum[(wm + 8 + g) * 2 + wh] = tsum[1];
        }
        __syncthreads();

        #pragma unroll
        for (int i = 0; i < 2; i++) {
            const int r = wm + g + 8 * i;
            l_run[i] = l_run[i] * fs[i] + psum[r * 2 + 0] + psum[r * 2 + 1];
        }

        #pragma unroll
        for (int dbl = 0; dbl < 8; dbl++) {
            O[dbl][0] *= fs[0];
            O[dbl][1] *= fs[0];
            O[dbl][2] *= fs[1];
            O[dbl][3] *= fs[1];
        }
        #pragma unroll
        for (int ks = 0; ks < 8; ks++) {
            const int k0 = ks * 8;
            u32 A[4];
            A[0] = __float_as_uint(Ss[(wm + g) * SPAD + k0 + t]);
            A[1] = __float_as_uint(Ss[(wm + 8 + g) * SPAD + k0 + t]);
            A[2] = __float_as_uint(Ss[(wm + g) * SPAD + k0 + t + 4]);
            A[3] = __float_as_uint(Ss[(wm + 8 + g) * SPAD + k0 + t + 4]);
            #pragma unroll
            for (int dbl = 0; dbl < 8; dbl++) {
                const int d0 = wd + dbl * 8;
                u32 Bv[2];
                Bv[0] = __float_as_uint(Vs[(k0 + t) * QPAD + d0 + g]);
                Bv[1] = __float_as_uint(Vs[(k0 + t + 4) * QPAD + d0 + g]);
                mma_tf32(O[dbl], A, Bv);
            }
        }
    }

    // Epilogue: O /= l, write fp16 (proj GEMM's A operand)
    float inv0 = 1.0f / l_run[0];
    float inv1 = 1.0f / l_run[1];
    const size_t obase = ((size_t)b * SEQ + (size_t)qt * QT) * DMODEL + hoff;
    #pragma unroll
    for (int dbl = 0; dbl < 8; dbl++) {
        const int col = wd + dbl * 8 + 2 * t;
        __half2 v0 = __floats2half2_rn(O[dbl][0] * inv0, O[dbl][1] * inv0);
        __half2 v1 = __floats2half2_rn(O[dbl][2] * inv1, O[dbl][3] * inv1);
        *(__half2*)&out[obase + (size_t)(wm + g) * DMODEL + col] = v0;
        *(__half2*)&out[obase + (size_t)(wm + 8 + g) * DMODEL + col] = v1;
    }
}

// ---------------------------------------------------------------------------
// Launch
// ---------------------------------------------------------------------------
extern "C" void kernel_launch(void* const* d_in, const int* in_sizes, int n_in,
                              void* d_out, int out_size) {
    const float* x     = (const float*)d_in[0];
    const float* Wqkv  = (const float*)d_in[1];
    const float* bqkv  = (const float*)d_in[2];
    const float* Wproj = (const float*)d_in[3];
    const float* bproj = (const float*)d_in[4];
    float* out = (float*)d_out;

    float* qkv;
    __half *atth, *xh, *wqkvh, *wprojh;
    cudaGetSymbolAddress((void**)&qkv, g_qkv);
    cudaGetSymbolAddress((void**)&atth, g_atth);
    cudaGetSymbolAddress((void**)&xh, g_xh);
    cudaGetSymbolAddress((void**)&wqkvh, g_wqkvh);
    cudaGetSymbolAddress((void**)&wprojh, g_wprojh);

    cudaFuncSetAttribute(attn_mma, cudaFuncAttributeMaxDynamicSharedMemorySize,
                         ATTN_SMEM_BYTES);
    cudaFuncSetAttribute(gemm_f16, cudaFuncAttributeMaxDynamicSharedMemorySize,
                         GEMM_SMEM_BYTES);

    // 0) Pre-convert inputs to fp16
    {
        int n4x = ROWS * DMODEL / 4;
        int n4q = DMODEL * QKV_N / 4;
        int n4p = DMODEL * DMODEL / 4;
        to_half<<<(n4x + 255) / 256, 256>>>(x, xh, n4x);
        to_half<<<(n4q + 255) / 256, 256>>>(Wqkv, wqkvh, n4q);
        to_half<<<(n4p + 255) / 256, 256>>>(Wproj, wprojh, n4p);
    }
    // 1) QKV GEMM: [4096,2048] @ [2048,6144] + bqkv  (fp16 in, fp32 out)
    {
        dim3 grid(QKV_N / GBN, ROWS / GBM);
        gemm_f16<<<grid, 256, GEMM_SMEM_BYTES>>>(xh, wqkvh, bqkv, qkv,
                                                 ROWS, QKV_N, DMODEL);
    }
    // 2) Causal attention (tf32 mma), fp16 output
    {
        dim3 grid(SEQ / QT, NHEAD, BATCH);
        attn_mma<<<grid, 256, ATTN_SMEM_BYTES>>>(qkv, atth);
    }
    // 3) Proj GEMM: [4096,2048] @ [2048,2048] + bproj
    {
        dim3 grid(DMODEL / GBN, ROWS / GBM);
        gemm_f16<<<grid, 256, GEMM_SMEM_BYTES>>>(atth, wprojh, bproj, out,
                                                 ROWS, DMODEL, DMODEL);
    }
}

// round 13
// speedup vs baseline: 2.2384x; 1.4128x over previous
#include <cuda_runtime.h>
#include <cuda_fp16.h>
#include <cstdint>
#include <math.h>
#include <math_constants.h>

typedef unsigned int u32;

// Problem constants
#define BATCH 2
#define SEQ   2048
#define DMODEL 2048
#define NHEAD 16
#define HDIM  128
#define ROWS  (BATCH * SEQ)          // 4096
#define QKV_N (3 * DMODEL)           // 6144

// Scratch (allocation-free rule: __device__ globals)
__device__ __half g_qkvh[(size_t)ROWS * QKV_N];      // fp16 QKV activations
__device__ __half g_atth[(size_t)ROWS * DMODEL];     // fp16 attention output
__device__ __half g_xh[(size_t)ROWS * DMODEL];       // fp16 x
__device__ __half g_wqkvh[(size_t)DMODEL * QKV_N];   // fp16 Wqkv
__device__ __half g_wprojh[(size_t)DMODEL * DMODEL]; // fp16 Wproj

// ---------------------------------------------------------------------------
// Helpers
// ---------------------------------------------------------------------------
__device__ __forceinline__ void cp_async16(u32 smem_addr, const void* gptr) {
    asm volatile("cp.async.cg.shared.global [%0], [%1], 16;\n"
                 :: "r"(smem_addr), "l"(gptr));
}
__device__ __forceinline__ void cp_commit() {
    asm volatile("cp.async.commit_group;\n" ::: "memory");
}
template <int N>
__device__ __forceinline__ void cp_wait() {
    asm volatile("cp.async.wait_group %0;\n" :: "n"(N) : "memory");
}

__device__ __forceinline__ void mma_f16(float* c, const u32* a, const u32* b) {
    asm volatile(
        "mma.sync.aligned.m16n8k16.row.col.f32.f16.f16.f32 "
        "{%0,%1,%2,%3}, {%4,%5,%6,%7}, {%8,%9}, {%0,%1,%2,%3};\n"
        : "+f"(c[0]), "+f"(c[1]), "+f"(c[2]), "+f"(c[3])
        : "r"(a[0]), "r"(a[1]), "r"(a[2]), "r"(a[3]), "r"(b[0]), "r"(b[1]));
}

__device__ __forceinline__ void ldsm_x4(u32* r, u32 addr) {
    asm volatile("ldmatrix.sync.aligned.m8n8.x4.shared.b16 {%0,%1,%2,%3}, [%4];"
                 : "=r"(r[0]), "=r"(r[1]), "=r"(r[2]), "=r"(r[3]) : "r"(addr));
}
__device__ __forceinline__ void ldsm_x4_t(u32* r, u32 addr) {
    asm volatile("ldmatrix.sync.aligned.m8n8.x4.trans.shared.b16 {%0,%1,%2,%3}, [%4];"
                 : "=r"(r[0]), "=r"(r[1]), "=r"(r[2]), "=r"(r[3]) : "r"(addr));
}

// ---------------------------------------------------------------------------
// Elementwise fp32 -> fp16 prepass
// ---------------------------------------------------------------------------
__global__ __launch_bounds__(256)
void to_half(const float* __restrict__ in, __half* __restrict__ out, int n4) {
    int i = blockIdx.x * 256 + threadIdx.x;
    if (i < n4) {
        float4 v = ((const float4*)in)[i];
        __half2* o = (__half2*)out;
        o[2 * i + 0] = __floats2half2_rn(v.x, v.y);
        o[2 * i + 1] = __floats2half2_rn(v.z, v.w);
    }
}

// ---------------------------------------------------------------------------
// FP16 tensor-core GEMM: C[M,N] = A[M,K] @ B[K,N] + bias[N]
// Output dtype templated: fp32 (final) or fp16 (intermediate).
// ---------------------------------------------------------------------------
#define GBM 128
#define GBN 128
#define GBK 32
#define HASTR 40
#define HBSTR 136
#define NSTAGE 3
#define A_TILE_H (GBM * HASTR)
#define B_TILE_H (GBK * HBSTR)
#define GEMM_SMEM_BYTES (NSTAGE * (A_TILE_H + B_TILE_H) * 2)   // 56832

template <bool HALF_OUT>
__global__ __launch_bounds__(256, 2)
void gemm_f16(const __half* __restrict__ A, const __half* __restrict__ B,
              const float* __restrict__ bias, void* __restrict__ Cv,
              int M, int N, int K) {
    extern __shared__ __half smh[];
    __half* Asm = smh;
    __half* Bsm = smh + NSTAGE * A_TILE_H;

    const int tid = threadIdx.x;
    const int lane = tid & 31;
    const int wid  = tid >> 5;
    const int g = lane >> 2;
    const int t = lane & 3;
    const int warp_m = (wid & 3) * 32;
    const int warp_n = (wid >> 2) * 64;

    const int rowBase = blockIdx.y * GBM;
    const int colBase = blockIdx.x * GBN;

    u32 asbase = (u32)__cvta_generic_to_shared(Asm);
    u32 bsbase = (u32)__cvta_generic_to_shared(Bsm);

    const int aRow = (lane & 7) + ((lane >> 3) & 1) * 8;
    const int aCol = (lane >> 4) * 8;
    const int bRow = (lane & 7) + ((lane >> 3) & 1) * 8;
    const int bColD = (lane >> 4) * 8;

    float acc[2][8][4];
    #pragma unroll
    for (int i = 0; i < 2; i++)
        #pragma unroll
        for (int j = 0; j < 8; j++)
            #pragma unroll
            for (int v = 0; v < 4; v++) acc[i][j][v] = 0.0f;

    const int NT = K / GBK;

    #pragma unroll
    for (int s = 0; s < NSTAGE - 1; s++) {
        const int k0g = s * GBK;
        u32 asd = asbase + (u32)s * (A_TILE_H * 2u);
        u32 bsd = bsbase + (u32)s * (B_TILE_H * 2u);
        #pragma unroll
        for (int it = 0; it < 2; it++) {
            int c = tid + it * 256;
            int ar = c >> 2, akc = (c & 3) * 8;
            cp_async16(asd + (u32)(ar * HASTR + akc) * 2u,
                       &A[(size_t)(rowBase + ar) * K + k0g + akc]);
            int br = c >> 4, bnc = (c & 15) * 8;
            cp_async16(bsd + (u32)(br * HBSTR + bnc) * 2u,
                       &B[(size_t)(k0g + br) * N + colBase + bnc]);
        }
        cp_commit();
    }

    for (int kt = 0; kt < NT; kt++) {
        if (kt + NSTAGE - 1 < NT) {
            const int s = (kt + NSTAGE - 1) % NSTAGE;
            const int k0g = (kt + NSTAGE - 1) * GBK;
            u32 asd = asbase + (u32)s * (A_TILE_H * 2u);
            u32 bsd = bsbase + (u32)s * (B_TILE_H * 2u);
            #pragma unroll
            for (int it = 0; it < 2; it++) {
                int c = tid + it * 256;
                int ar = c >> 2, akc = (c & 3) * 8;
                cp_async16(asd + (u32)(ar * HASTR + akc) * 2u,
                           &A[(size_t)(rowBase + ar) * K + k0g + akc]);
                int br = c >> 4, bnc = (c & 15) * 8;
                cp_async16(bsd + (u32)(br * HBSTR + bnc) * 2u,
                           &B[(size_t)(k0g + br) * N + colBase + bnc]);
            }
        }
        cp_commit();
        cp_wait<NSTAGE - 1>();
        __syncthreads();

        const int buf = kt % NSTAGE;
        const u32 asb = asbase + (u32)buf * (A_TILE_H * 2u);
        const u32 bsb = bsbase + (u32)buf * (B_TILE_H * 2u);

        #pragma unroll
        for (int ks = 0; ks < 2; ks++) {
            const int k0 = ks * 16;
            u32 af[2][4];
            u32 bf[8][2];
            #pragma unroll
            for (int mt = 0; mt < 2; mt++) {
                u32 addr = asb + (u32)((warp_m + mt * 16 + aRow) * HASTR
                                       + k0 + aCol) * 2u;
                ldsm_x4(af[mt], addr);
            }
            #pragma unroll
            for (int nbp = 0; nbp < 4; nbp++) {
                u32 r4[4];
                u32 addr = bsb + (u32)((k0 + bRow) * HBSTR
                                       + warp_n + nbp * 16 + bColD) * 2u;
                ldsm_x4_t(r4, addr);
                bf[nbp * 2 + 0][0] = r4[0]; bf[nbp * 2 + 0][1] = r4[1];
                bf[nbp * 2 + 1][0] = r4[2]; bf[nbp * 2 + 1][1] = r4[3];
            }
            #pragma unroll
            for (int mt = 0; mt < 2; mt++)
                #pragma unroll
                for (int nt = 0; nt < 8; nt++)
                    mma_f16(acc[mt][nt], af[mt], bf[nt]);
        }
        __syncthreads();
    }

    #pragma unroll
    for (int mt = 0; mt < 2; mt++) {
        int row = rowBase + warp_m + mt * 16 + g;
        #pragma unroll
        for (int nt = 0; nt < 8; nt++) {
            int col = colBase + warp_n + nt * 8 + 2 * t;
            float b0 = bias[col], b1 = bias[col + 1];
            if (HALF_OUT) {
                __half* C = (__half*)Cv;
                *(__half2*)&C[(size_t)row * N + col] =
                    __floats2half2_rn(acc[mt][nt][0] + b0, acc[mt][nt][1] + b1);
                *(__half2*)&C[(size_t)(row + 8) * N + col] =
                    __floats2half2_rn(acc[mt][nt][2] + b0, acc[mt][nt][3] + b1);
            } else {
                float* C = (float*)Cv;
                *(float2*)&C[(size_t)row * N + col] =
                    make_float2(acc[mt][nt][0] + b0, acc[mt][nt][1] + b1);
                *(float2*)&C[(size_t)(row + 8) * N + col] =
                    make_float2(acc[mt][nt][2] + b0, acc[mt][nt][3] + b1);
            }
        }
    }
}

// ---------------------------------------------------------------------------
// Flash attention, fp16 ldmatrix + m16n8k16 mma for QK^T and P@V.
// Grid: (S/64, H, B), 256 threads (8 warps): wm=(w&3)*16 q-rows, wh=w>>2.
//   S: rows [wm,wm+16) x key-cols [wh*32,+32); O: rows x d-cols [wh*64,+64).
// ---------------------------------------------------------------------------
#define QT 64
#define KSTR 136   // halves; 272B = 16 mod 128 -> conflict-free ldsm
#define SSTR 72    // halves; 144B = 16 mod 128
#define AQ_H (QT * KSTR)            // 8704 halves
#define AS_H (QT * SSTR)            // 4608 halves
#define ATTN_SMEM_BYTES ((3 * AQ_H + AS_H) * 2 + 2 * 128 * 4)   // 62464

__global__ __launch_bounds__(256, 2)
void attn_f16(const __half* __restrict__ qkv, __half* __restrict__ out) {
    extern __shared__ __half smha[];
    __half* Qs = smha;                    // [64][136]
    __half* Ks = Qs + AQ_H;               // [64][136]
    __half* Vs = Ks + AQ_H;               // [64][136]
    __half* Ss = Vs + AQ_H;               // [64][72]  (P, fp16)
    float* pmax = (float*)(Ss + AS_H);    // [64][2]
    float* psum = pmax + 128;             // [64][2]

    const int qt  = gridDim.x - 1 - blockIdx.x;
    const int h   = blockIdx.y;
    const int b   = blockIdx.z;
    const int tid = threadIdx.x;
    const int lane = tid & 31;
    const int w    = tid >> 5;
    const int g    = lane >> 2;
    const int t    = lane & 3;
    const int wm   = (w & 3) * 16;
    const int wh   = w >> 2;
    const int wn   = wh * 32;
    const int wd   = wh * 64;

    // ldmatrix address components
    const int aRow = (lane & 7) + ((lane >> 3) & 1) * 8;  // A: m16 x k16
    const int aCol = (lane >> 4) * 8;
    const int nRow = (lane & 7) + (lane >> 4) * 8;        // B from [n][k]
    const int kCol = ((lane >> 3) & 1) * 8;
    const int bRow = (lane & 7) + ((lane >> 3) & 1) * 8;  // B from [k][n] (trans)
    const int bColD = (lane >> 4) * 8;

    const u32 qs_u = (u32)__cvta_generic_to_shared(Qs);
    const u32 ks_u = (u32)__cvta_generic_to_shared(Ks);
    const u32 vs_u = (u32)__cvta_generic_to_shared(Vs);
    const u32 ss_u = (u32)__cvta_generic_to_shared(Ss);

    const float scale = 0.08838834764831845f;   // 1/sqrt(128)
    const size_t base = (size_t)b * SEQ * QKV_N;
    const int hoff = h * HDIM;

    // Load Q tile (fp16, 8 halves per float4)
    for (int idx = tid; idx < QT * 16; idx += 256) {
        int r  = idx >> 4;
        int c8 = (idx & 15) * 8;
        *(float4*)&Qs[r * KSTR + c8] =
            *(const float4*)&qkv[base + (size_t)(qt * QT + r) * QKV_N + hoff + c8];
    }

    float m_run[2] = { -CUDART_INF_F, -CUDART_INF_F };
    float l_run[2] = { 0.0f, 0.0f };
    float O[8][4];
    #pragma unroll
    for (int dbl = 0; dbl < 8; dbl++)
        #pragma unroll
        for (int v = 0; v < 4; v++) O[dbl][v] = 0.0f;

    for (int kt = 0; kt <= qt; kt++) {
        __syncthreads();   // prev iter done with Ks/Vs/Ss (Qs visible iter 0)
        for (int idx = tid; idx < QT * 16; idx += 256) {
            int r  = idx >> 4;
            int c8 = (idx & 15) * 8;
            size_t rowoff = base + (size_t)(kt * QT + r) * QKV_N + hoff;
            *(float4*)&Ks[r * KSTR + c8] = *(const float4*)&qkv[rowoff + DMODEL + c8];
            *(float4*)&Vs[r * KSTR + c8] = *(const float4*)&qkv[rowoff + 2 * DMODEL + c8];
        }
        __syncthreads();

        // ---- S = Q @ K^T : m16 x n32 x k128 ----
        float sa[4][4];
        #pragma unroll
        for (int nb = 0; nb < 4; nb++)
            #pragma unroll
            for (int v = 0; v < 4; v++) sa[nb][v] = 0.0f;

        #pragma unroll
        for (int ks = 0; ks < 8; ks++) {
            const int k0 = ks * 16;
            u32 A4[4];
            ldsm_x4(A4, qs_u + (u32)((wm + aRow) * KSTR + k0 + aCol) * 2u);
            #pragma unroll
            for (int nbp = 0; nbp < 2; nbp++) {
                u32 r4[4];
                ldsm_x4(r4, ks_u + (u32)((wn + nbp * 16 + nRow) * KSTR
                                         + k0 + kCol) * 2u);
                u32 b0[2] = { r4[0], r4[1] };
                u32 b1[2] = { r4[2], r4[3] };
                mma_f16(sa[nbp * 2 + 0], A4, b0);
                mma_f16(sa[nbp * 2 + 1], A4, b1);
            }
        }

        // scale + causal mask
        #pragma unroll
        for (int nb = 0; nb < 4; nb++)
            #pragma unroll
            for (int v = 0; v < 4; v++) sa[nb][v] *= scale;
        if (kt == qt) {
            #pragma unroll
            for (int nb = 0; nb < 4; nb++) {
                const int c0 = wn + nb * 8 + 2 * t;
                if (c0     > wm + g)     sa[nb][0] = -CUDART_INF_F;
                if (c0 + 1 > wm + g)     sa[nb][1] = -CUDART_INF_F;
                if (c0     > wm + 8 + g) sa[nb][2] = -CUDART_INF_F;
                if (c0 + 1 > wm + 8 + g) sa[nb][3] = -CUDART_INF_F;
            }
        }

        // ---- row max (this warp's 32-col half), cross-half via smem ----
        float tmax[2];
        tmax[0] = fmaxf(fmaxf(sa[0][0], sa[0][1]), fmaxf(sa[1][0], sa[1][1]));
        tmax[0] = fmaxf(tmax[0], fmaxf(fmaxf(sa[2][0], sa[2][1]), fmaxf(sa[3][0], sa[3][1])));
        tmax[1] = fmaxf(fmaxf(sa[0][2], sa[0][3]), fmaxf(sa[1][2], sa[1][3]));
        tmax[1] = fmaxf(tmax[1], fmaxf(fmaxf(sa[2][2], sa[2][3]), fmaxf(sa[3][2], sa[3][3])));
        #pragma unroll
        for (int i = 0; i < 2; i++) {
            tmax[i] = fmaxf(tmax[i], __shfl_xor_sync(0xffffffffu, tmax[i], 1));
            tmax[i] = fmaxf(tmax[i], __shfl_xor_sync(0xffffffffu, tmax[i], 2));
        }
        if (t == 0) {
            pmax[(wm + g) * 2 + wh]     = tmax[0];
            pmax[(wm + 8 + g) * 2 + wh] = tmax[1];
        }
        __syncthreads();

        float fs[2];
        #pragma unroll
        for (int i = 0; i < 2; i++) {
            const int r = wm + g + 8 * i;
            float mt2 = fmaxf(pmax[r * 2 + 0], pmax[r * 2 + 1]);
            float mn = fmaxf(m_run[i], mt2);
            fs[i] = __expf(m_run[i] - mn);
            m_run[i] = mn;
        }

        // ---- p = exp(s - m), write fp16 P, partial row sums ----
        float tsum[2] = { 0.0f, 0.0f };
        #pragma unroll
        for (int nb = 0; nb < 4; nb++) {
            float p0 = __expf(sa[nb][0] - m_run[0]);
            float p1 = __expf(sa[nb][1] - m_run[0]);
            float p2 = __expf(sa[nb][2] - m_run[1]);
            float p3 = __expf(sa[nb][3] - m_run[1]);
            tsum[0] += p0 + p1;
            tsum[1] += p2 + p3;
            const int col = wn + nb * 8 + 2 * t;
            *(__half2*)&Ss[(wm + g) * SSTR + col]     = __floats2half2_rn(p0, p1);
            *(__half2*)&Ss[(wm + 8 + g) * SSTR + col] = __floats2half2_rn(p2, p3);
        }
        #pragma unroll
        for (int i = 0; i < 2; i++) {
            tsum[i] += __shfl_xor_sync(0xffffffffu, tsum[i], 1);
            tsum[i] += __shfl_xor_sync(0xffffffffu, tsum[i], 2);
        }
        if (t == 0) {
            psum[(wm + g) * 2 + wh]     = tsum[0];
            psum[(wm + 8 + g) * 2 + wh] = tsum[1];
        }
        __syncthreads();   // covers Ss and psum

        #pragma unroll
        for (int i = 0; i < 2; i++) {
            const int r = wm + g + 8 * i;
            l_run[i] = l_run[i] * fs[i] + psum[r * 2 + 0] + psum[r * 2 + 1];
        }

        // ---- O = O*fs + P @ V : m16 x n64 x k64 ----
        #pragma unroll
        for (int dbl = 0; dbl < 8; dbl++) {
            O[dbl][0] *= fs[0];
            O[dbl][1] *= fs[0];
            O[dbl][2] *= fs[1];
            O[dbl][3] *= fs[1];
        }
        #pragma unroll
        for (int ks = 0; ks < 4; ks++) {
            const int k0 = ks * 16;
            u32 A4[4];
            ldsm_x4(A4, ss_u + (u32)((wm + aRow) * SSTR + k0 + aCol) * 2u);
            #pragma unroll
            for (int nbp = 0; nbp < 4; nbp++) {
                u32 r4[4];
                ldsm_x4_t(r4, vs_u + (u32)((k0 + bRow) * KSTR
                                           + wd + nbp * 16 + bColD) * 2u);
                u32 b0[2] = { r4[0], r4[1] };
                u32 b1[2] = { r4[2], r4[3] };
                mma_f16(O[nbp * 2 + 0], A4, b0);
                mma_f16(O[nbp * 2 + 1], A4, b1);
            }
        }
    }

    // Epilogue: O /= l, write fp16
    float inv0 = 1.0f / l_run[0];
    float inv1 = 1.0f / l_run[1];
    const size_t obase = ((size_t)b * SEQ + (size_t)qt * QT) * DMODEL + hoff;
    #pragma unroll
    for (int dbl = 0; dbl < 8; dbl++) {
        const int col = wd + dbl * 8 + 2 * t;
        *(__half2*)&out[obase + (size_t)(wm + g) * DMODEL + col] =
            __floats2half2_rn(O[dbl][0] * inv0, O[dbl][1] * inv0);
        *(__half2*)&out[obase + (size_t)(wm + 8 + g) * DMODEL + col] =
            __floats2half2_rn(O[dbl][2] * inv1, O[dbl][3] * inv1);
    }
}

// ---------------------------------------------------------------------------
// Launch
// ---------------------------------------------------------------------------
extern "C" void kernel_launch(void* const* d_in, const int* in_sizes, int n_in,
                              void* d_out, int out_size) {
    const float* x     = (const float*)d_in[0];
    const float* Wqkv  = (const float*)d_in[1];
    const float* bqkv  = (const float*)d_in[2];
    const float* Wproj = (const float*)d_in[3];
    const float* bproj = (const float*)d_in[4];
    float* out = (float*)d_out;

    __half *qkvh, *atth, *xh, *wqkvh, *wprojh;
    cudaGetSymbolAddress((void**)&qkvh, g_qkvh);
    cudaGetSymbolAddress((void**)&atth, g_atth);
    cudaGetSymbolAddress((void**)&xh, g_xh);
    cudaGetSymbolAddress((void**)&wqkvh, g_wqkvh);
    cudaGetSymbolAddress((void**)&wprojh, g_wprojh);

    cudaFuncSetAttribute(attn_f16, cudaFuncAttributeMaxDynamicSharedMemorySize,
                         ATTN_SMEM_BYTES);
    cudaFuncSetAttribute(gemm_f16<true>, cudaFuncAttributeMaxDynamicSharedMemorySize,
                         GEMM_SMEM_BYTES);
    cudaFuncSetAttribute(gemm_f16<false>, cudaFuncAttributeMaxDynamicSharedMemorySize,
                         GEMM_SMEM_BYTES);

    // 0) Pre-convert inputs to fp16
    {
        int n4x = ROWS * DMODEL / 4;
        int n4q = DMODEL * QKV_N / 4;
        int n4p = DMODEL * DMODEL / 4;
        to_half<<<(n4x + 255) / 256, 256>>>(x, xh, n4x);
        to_half<<<(n4q + 255) / 256, 256>>>(Wqkv, wqkvh, n4q);
        to_half<<<(n4p + 255) / 256, 256>>>(Wproj, wprojh, n4p);
    }
    // 1) QKV GEMM -> fp16 qkv
    {
        dim3 grid(QKV_N / GBN, ROWS / GBM);
        gemm_f16<true><<<grid, 256, GEMM_SMEM_BYTES>>>(xh, wqkvh, bqkv, qkvh,
                                                       ROWS, QKV_N, DMODEL);
    }
    // 2) Causal attention (fp16 mma) -> fp16
    {
        dim3 grid(SEQ / QT, NHEAD, BATCH);
        attn_f16<<<grid, 256, ATTN_SMEM_BYTES>>>(qkvh, atth);
    }
    // 3) Proj GEMM -> fp32 out
    {
        dim3 grid(DMODEL / GBN, ROWS / GBM);
        gemm_f16<false><<<grid, 256, GEMM_SMEM_BYTES>>>(atth, wprojh, bproj, out,
                                                        ROWS, DMODEL, DMODEL);
    }
}

// round 15
// speedup vs baseline: 2.4047x; 1.0743x over previous
#include <cuda_runtime.h>
#include <cuda_fp16.h>
#include <cstdint>
#include <math.h>
#include <math_constants.h>

typedef unsigned int u32;

// Problem constants
#define BATCH 2
#define SEQ   2048
#define DMODEL 2048
#define NHEAD 16
#define HDIM  128
#define ROWS  (BATCH * SEQ)          // 4096
#define QKV_N (3 * DMODEL)           // 6144

// Scratch (allocation-free rule: __device__ globals)
__device__ __half g_qkvh[(size_t)ROWS * QKV_N];      // fp16 QKV activations
__device__ __half g_atth[(size_t)ROWS * DMODEL];     // fp16 attention output
__device__ __half g_xh[(size_t)ROWS * DMODEL];       // fp16 x
__device__ __half g_wqkvh[(size_t)DMODEL * QKV_N];   // fp16 Wqkv
__device__ __half g_wprojh[(size_t)DMODEL * DMODEL]; // fp16 Wproj

// ---------------------------------------------------------------------------
// Helpers
// ---------------------------------------------------------------------------
__device__ __forceinline__ void cp_async16(u32 smem_addr, const void* gptr) {
    asm volatile("cp.async.cg.shared.global [%0], [%1], 16;\n"
                 :: "r"(smem_addr), "l"(gptr));
}
__device__ __forceinline__ void cp_commit() {
    asm volatile("cp.async.commit_group;\n" ::: "memory");
}
template <int N>
__device__ __forceinline__ void cp_wait() {
    asm volatile("cp.async.wait_group %0;\n" :: "n"(N) : "memory");
}

__device__ __forceinline__ void mma_f16(float* c, const u32* a, const u32* b) {
    asm volatile(
        "mma.sync.aligned.m16n8k16.row.col.f32.f16.f16.f32 "
        "{%0,%1,%2,%3}, {%4,%5,%6,%7}, {%8,%9}, {%0,%1,%2,%3};\n"
        : "+f"(c[0]), "+f"(c[1]), "+f"(c[2]), "+f"(c[3])
        : "r"(a[0]), "r"(a[1]), "r"(a[2]), "r"(a[3]), "r"(b[0]), "r"(b[1]));
}
__device__ __forceinline__ void ldsm_x4(u32* r, u32 addr) {
    asm volatile("ldmatrix.sync.aligned.m8n8.x4.shared.b16 {%0,%1,%2,%3}, [%4];"
                 : "=r"(r[0]), "=r"(r[1]), "=r"(r[2]), "=r"(r[3]) : "r"(addr));
}
__device__ __forceinline__ void ldsm_x4_t(u32* r, u32 addr) {
    asm volatile("ldmatrix.sync.aligned.m8n8.x4.trans.shared.b16 {%0,%1,%2,%3}, [%4];"
                 : "=r"(r[0]), "=r"(r[1]), "=r"(r[2]), "=r"(r[3]) : "r"(addr));
}

// ---------------------------------------------------------------------------
// Elementwise fp32 -> fp16 prepass
// ---------------------------------------------------------------------------
__global__ __launch_bounds__(256)
void to_half(const float* __restrict__ in, __half* __restrict__ out, int n4) {
    int i = blockIdx.x * 256 + threadIdx.x;
    if (i < n4) {
        float4 v = ((const float4*)in)[i];
        __half2* o = (__half2*)out;
        o[2 * i + 0] = __floats2half2_rn(v.x, v.y);
        o[2 * i + 1] = __floats2half2_rn(v.z, v.w);
    }
}

// ---------------------------------------------------------------------------
// FP16 tensor-core GEMM: C[M,N] = A[M,K] @ B[K,N] + bias[N]
// 128x128 tile, BK=32, 3-stage cp.async, 128 threads (4 warps),
// warp tile 64x64 (8 ldsm per 32 mma -> half the L1 traffic per FLOP).
// ---------------------------------------------------------------------------
#define GBM 128
#define GBN 128
#define GBK 32
#define HASTR 40
#define HBSTR 136
#define NSTAGE 3
#define A_TILE_H (GBM * HASTR)
#define B_TILE_H (GBK * HBSTR)
#define GEMM_SMEM_BYTES (NSTAGE * (A_TILE_H + B_TILE_H) * 2)   // 56832

template <bool HALF_OUT>
__global__ __launch_bounds__(128)
void gemm_f16(const __half* __restrict__ A, const __half* __restrict__ B,
              const float* __restrict__ bias, void* __restrict__ Cv,
              int M, int N, int K) {
    extern __shared__ __half smh[];
    __half* Asm = smh;
    __half* Bsm = smh + NSTAGE * A_TILE_H;

    const int tid = threadIdx.x;
    const int lane = tid & 31;
    const int wid  = tid >> 5;
    const int g = lane >> 2;
    const int t = lane & 3;
    const int warp_m = (wid & 1) * 64;
    const int warp_n = (wid >> 1) * 64;

    const int rowBase = blockIdx.y * GBM;
    const int colBase = blockIdx.x * GBN;

    u32 asbase = (u32)__cvta_generic_to_shared(Asm);
    u32 bsbase = (u32)__cvta_generic_to_shared(Bsm);

    const int aRow = (lane & 7) + ((lane >> 3) & 1) * 8;
    const int aCol = (lane >> 4) * 8;
    const int bRow = (lane & 7) + ((lane >> 3) & 1) * 8;
    const int bColD = (lane >> 4) * 8;

    float acc[4][8][4];
    #pragma unroll
    for (int i = 0; i < 4; i++)
        #pragma unroll
        for (int j = 0; j < 8; j++)
            #pragma unroll
            for (int v = 0; v < 4; v++) acc[i][j][v] = 0.0f;

    const int NT = K / GBK;

    // cp.async: A 512 chunks (4/row), B 512 chunks (16/row); 4 iters each
    #pragma unroll
    for (int s = 0; s < NSTAGE - 1; s++) {
        const int k0g = s * GBK;
        u32 asd = asbase + (u32)s * (A_TILE_H * 2u);
        u32 bsd = bsbase + (u32)s * (B_TILE_H * 2u);
        #pragma unroll
        for (int it = 0; it < 4; it++) {
            int c = tid + it * 128;
            int ar = c >> 2, akc = (c & 3) * 8;
            cp_async16(asd + (u32)(ar * HASTR + akc) * 2u,
                       &A[(size_t)(rowBase + ar) * K + k0g + akc]);
            int br = c >> 4, bnc = (c & 15) * 8;
            cp_async16(bsd + (u32)(br * HBSTR + bnc) * 2u,
                       &B[(size_t)(k0g + br) * N + colBase + bnc]);
        }
        cp_commit();
    }

    for (int kt = 0; kt < NT; kt++) {
        if (kt + NSTAGE - 1 < NT) {
            const int s = (kt + NSTAGE - 1) % NSTAGE;
            const int k0g = (kt + NSTAGE - 1) * GBK;
            u32 asd = asbase + (u32)s * (A_TILE_H * 2u);
            u32 bsd = bsbase + (u32)s * (B_TILE_H * 2u);
            #pragma unroll
            for (int it = 0; it < 4; it++) {
                int c = tid + it * 128;
                int ar = c >> 2, akc = (c & 3) * 8;
                cp_async16(asd + (u32)(ar * HASTR + akc) * 2u,
                           &A[(size_t)(rowBase + ar) * K + k0g + akc]);
                int br = c >> 4, bnc = (c & 15) * 8;
                cp_async16(bsd + (u32)(br * HBSTR + bnc) * 2u,
                           &B[(size_t)(k0g + br) * N + colBase + bnc]);
            }
        }
        cp_commit();
        cp_wait<NSTAGE - 1>();
        __syncthreads();

        const int buf = kt % NSTAGE;
        const u32 asb = asbase + (u32)buf * (A_TILE_H * 2u);
        const u32 bsb = bsbase + (u32)buf * (B_TILE_H * 2u);

        #pragma unroll
        for (int ks = 0; ks < 2; ks++) {
            const int k0 = ks * 16;
            u32 af[4][4];
            #pragma unroll
            for (int mt = 0; mt < 4; mt++) {
                u32 addr = asb + (u32)((warp_m + mt * 16 + aRow) * HASTR
                                       + k0 + aCol) * 2u;
                ldsm_x4(af[mt], addr);
            }
            #pragma unroll
            for (int nbp = 0; nbp < 4; nbp++) {
                u32 r4[4];
                u32 addr = bsb + (u32)((k0 + bRow) * HBSTR
                                       + warp_n + nbp * 16 + bColD) * 2u;
                ldsm_x4_t(r4, addr);
                u32 b0[2] = { r4[0], r4[1] };
                u32 b1[2] = { r4[2], r4[3] };
                #pragma unroll
                for (int mt = 0; mt < 4; mt++) {
                    mma_f16(acc[mt][nbp * 2 + 0], af[mt], b0);
                    mma_f16(acc[mt][nbp * 2 + 1], af[mt], b1);
                }
            }
        }
        __syncthreads();
    }

    #pragma unroll
    for (int mt = 0; mt < 4; mt++) {
        int row = rowBase + warp_m + mt * 16 + g;
        #pragma unroll
        for (int nt = 0; nt < 8; nt++) {
            int col = colBase + warp_n + nt * 8 + 2 * t;
            float b0 = bias[col], b1 = bias[col + 1];
            if (HALF_OUT) {
                __half* C = (__half*)Cv;
                *(__half2*)&C[(size_t)row * N + col] =
                    __floats2half2_rn(acc[mt][nt][0] + b0, acc[mt][nt][1] + b1);
                *(__half2*)&C[(size_t)(row + 8) * N + col] =
                    __floats2half2_rn(acc[mt][nt][2] + b0, acc[mt][nt][3] + b1);
            } else {
                float* C = (float*)Cv;
                *(float2*)&C[(size_t)row * N + col] =
                    make_float2(acc[mt][nt][0] + b0, acc[mt][nt][1] + b1);
                *(float2*)&C[(size_t)(row + 8) * N + col] =
                    make_float2(acc[mt][nt][2] + b0, acc[mt][nt][3] + b1);
            }
        }
    }
}

// ---------------------------------------------------------------------------
// Flash attention, fp16 ldsm+mma, INTRA-WARP softmax.
// Grid: (S/64, H, B), 128 threads (4 warps). Warp w owns q-rows
// [w*16, w*16+16) x ALL 64 key-cols (S) and all 128 d-cols (O).
// Row max/sum complete via shfl over lane bits 0-1 (the fragment col threads).
// P is warp-private (written+read by same warp) -> __syncwarp only.
// ---------------------------------------------------------------------------
#define QT 64
#define KSTR 136   // halves; 272B = 16 mod 128 -> conflict-free ldsm
#define SSTR 72    // halves; 144B = 16 mod 128
#define AQ_H (QT * KSTR)
#define AS_H (QT * SSTR)
#define ATTN_SMEM_BYTES ((3 * AQ_H + AS_H) * 2)    // 61440

__global__ __launch_bounds__(128)
void attn_f16(const __half* __restrict__ qkv, __half* __restrict__ out) {
    extern __shared__ __half smha[];
    __half* Qs = smha;                    // [64][136]
    __half* Ks = Qs + AQ_H;               // [64][136]
    __half* Vs = Ks + AQ_H;               // [64][136]
    __half* Ss = Vs + AQ_H;               // [64][72]

    const int qt  = gridDim.x - 1 - blockIdx.x;
    const int h   = blockIdx.y;
    const int b   = blockIdx.z;
    const int tid = threadIdx.x;
    const int lane = tid & 31;
    const int w    = tid >> 5;
    const int g    = lane >> 2;
    const int t    = lane & 3;
    const int wm   = w * 16;              // q-row stripe

    const int aRow = (lane & 7) + ((lane >> 3) & 1) * 8;
    const int aCol = (lane >> 4) * 8;
    const int nRow = (lane & 7) + (lane >> 4) * 8;
    const int kCol = ((lane >> 3) & 1) * 8;
    const int bRow = (lane & 7) + ((lane >> 3) & 1) * 8;
    const int bColD = (lane >> 4) * 8;

    const u32 qs_u = (u32)__cvta_generic_to_shared(Qs);
    const u32 ks_u = (u32)__cvta_generic_to_shared(Ks);
    const u32 vs_u = (u32)__cvta_generic_to_shared(Vs);
    const u32 ss_u = (u32)__cvta_generic_to_shared(Ss);

    const float scale = 0.08838834764831845f;
    const size_t base = (size_t)b * SEQ * QKV_N;
    const int hoff = h * HDIM;

    // Load Q tile (1024 16B-chunks, 8 iters)
    for (int idx = tid; idx < QT * 16; idx += 128) {
        int r  = idx >> 4;
        int c8 = (idx & 15) * 8;
        *(float4*)&Qs[r * KSTR + c8] =
            *(const float4*)&qkv[base + (size_t)(qt * QT + r) * QKV_N + hoff + c8];
    }

    float m_run[2] = { -CUDART_INF_F, -CUDART_INF_F };
    float l_run[2] = { 0.0f, 0.0f };
    float O[16][4];
    #pragma unroll
    for (int dbl = 0; dbl < 16; dbl++)
        #pragma unroll
        for (int v = 0; v < 4; v++) O[dbl][v] = 0.0f;

    for (int kt = 0; kt <= qt; kt++) {
        __syncthreads();   // prev iter done with Ks/Vs (Qs visible iter 0)
        for (int idx = tid; idx < QT * 16; idx += 128) {
            int r  = idx >> 4;
            int c8 = (idx & 15) * 8;
            size_t rowoff = base + (size_t)(kt * QT + r) * QKV_N + hoff;
            *(float4*)&Ks[r * KSTR + c8] = *(const float4*)&qkv[rowoff + DMODEL + c8];
            *(float4*)&Vs[r * KSTR + c8] = *(const float4*)&qkv[rowoff + 2 * DMODEL + c8];
        }
        __syncthreads();

        // ---- S = Q @ K^T : m16 x n64 x k128 ----
        float sa[8][4];
        #pragma unroll
        for (int nb = 0; nb < 8; nb++)
            #pragma unroll
            for (int v = 0; v < 4; v++) sa[nb][v] = 0.0f;

        #pragma unroll
        for (int ks = 0; ks < 8; ks++) {
            const int k0 = ks * 16;
            u32 A4[4];
            ldsm_x4(A4, qs_u + (u32)((wm + aRow) * KSTR + k0 + aCol) * 2u);
            #pragma unroll
            for (int nbp = 0; nbp < 4; nbp++) {
                u32 r4[4];
                ldsm_x4(r4, ks_u + (u32)((nbp * 16 + nRow) * KSTR
                                         + k0 + kCol) * 2u);
                u32 b0[2] = { r4[0], r4[1] };
                u32 b1[2] = { r4[2], r4[3] };
                mma_f16(sa[nbp * 2 + 0], A4, b0);
                mma_f16(sa[nbp * 2 + 1], A4, b1);
            }
        }

        // scale + causal mask (fragment rows wm+g / wm+8+g, cols nb*8+2t+{0,1})
        #pragma unroll
        for (int nb = 0; nb < 8; nb++)
            #pragma unroll
            for (int v = 0; v < 4; v++) sa[nb][v] *= scale;
        if (kt == qt) {
            #pragma unroll
            for (int nb = 0; nb < 8; nb++) {
                const int c0 = nb * 8 + 2 * t;
                if (c0     > wm + g)     sa[nb][0] = -CUDART_INF_F;
                if (c0 + 1 > wm + g)     sa[nb][1] = -CUDART_INF_F;
                if (c0     > wm + 8 + g) sa[nb][2] = -CUDART_INF_F;
                if (c0 + 1 > wm + 8 + g) sa[nb][3] = -CUDART_INF_F;
            }
        }

        // ---- full row max within warp: in-thread over 8 nb, shfl over t ----
        float tmax[2] = { -CUDART_INF_F, -CUDART_INF_F };
        #pragma unroll
        for (int nb = 0; nb < 8; nb++) {
            tmax[0] = fmaxf(tmax[0], fmaxf(sa[nb][0], sa[nb][1]));
            tmax[1] = fmaxf(tmax[1], fmaxf(sa[nb][2], sa[nb][3]));
        }
        #pragma unroll
        for (int i = 0; i < 2; i++) {
            tmax[i] = fmaxf(tmax[i], __shfl_xor_sync(0xffffffffu, tmax[i], 1));
            tmax[i] = fmaxf(tmax[i], __shfl_xor_sync(0xffffffffu, tmax[i], 2));
        }

        float fs[2];
        #pragma unroll
        for (int i = 0; i < 2; i++) {
            float mn = fmaxf(m_run[i], tmax[i]);
            fs[i] = __expf(m_run[i] - mn);   // 0 on first iter
            m_run[i] = mn;
        }

        // ---- p = exp(s - m), store fp16 P (warp-private rows), row sums ----
        float tsum[2] = { 0.0f, 0.0f };
        #pragma unroll
        for (int nb = 0; nb < 8; nb++) {
            float p0 = __expf(sa[nb][0] - m_run[0]);
            float p1 = __expf(sa[nb][1] - m_run[0]);
            float p2 = __expf(sa[nb][2] - m_run[1]);
            float p3 = __expf(sa[nb][3] - m_run[1]);
            tsum[0] += p0 + p1;
            tsum[1] += p2 + p3;
            const int col = nb * 8 + 2 * t;
            *(__half2*)&Ss[(wm + g) * SSTR + col]     = __floats2half2_rn(p0, p1);
            *(__half2*)&Ss[(wm + 8 + g) * SSTR + col] = __floats2half2_rn(p2, p3);
        }
        #pragma unroll
        for (int i = 0; i < 2; i++) {
            tsum[i] += __shfl_xor_sync(0xffffffffu, tsum[i], 1);
            tsum[i] += __shfl_xor_sync(0xffffffffu, tsum[i], 2);
            l_run[i] = l_run[i] * fs[i] + tsum[i];
        }
        __syncwarp();   // P visible to this warp's ldsm

        // ---- O = O*fs + P @ V : m16 x n128 x k64 ----
        #pragma unroll
        for (int dbl = 0; dbl < 16; dbl++) {
            O[dbl][0] *= fs[0];
            O[dbl][1] *= fs[0];
            O[dbl][2] *= fs[1];
            O[dbl][3] *= fs[1];
        }
        #pragma unroll
        for (int ks = 0; ks < 4; ks++) {
            const int k0 = ks * 16;
            u32 A4[4];
            ldsm_x4(A4, ss_u + (u32)((wm + aRow) * SSTR + k0 + aCol) * 2u);
            #pragma unroll
            for (int nbp = 0; nbp < 8; nbp++) {
                u32 r4[4];
                ldsm_x4_t(r4, vs_u + (u32)((k0 + bRow) * KSTR
                                           + nbp * 16 + bColD) * 2u);
                u32 b0[2] = { r4[0], r4[1] };
                u32 b1[2] = { r4[2], r4[3] };
                mma_f16(O[nbp * 2 + 0], A4, b0);
                mma_f16(O[nbp * 2 + 1], A4, b1);
            }
        }
    }

    // Epilogue: O /= l, write fp16 (full d=128 per warp)
    float inv0 = 1.0f / l_run[0];
    float inv1 = 1.0f / l_run[1];
    const size_t obase = ((size_t)b * SEQ + (size_t)qt * QT) * DMODEL + hoff;
    #pragma unroll
    for (int dbl = 0; dbl < 16; dbl++) {
        const int col = dbl * 8 + 2 * t;
        *(__half2*)&out[obase + (size_t)(wm + g) * DMODEL + col] =
            __floats2half2_rn(O[dbl][0] * inv0, O[dbl][1] * inv0);
        *(__half2*)&out[obase + (size_t)(wm + 8 + g) * DMODEL + col] =
            __floats2half2_rn(O[dbl][2] * inv1, O[dbl][3] * inv1);
    }
}

// ---------------------------------------------------------------------------
// Launch
// ---------------------------------------------------------------------------
extern "C" void kernel_launch(void* const* d_in, const int* in_sizes, int n_in,
                              void* d_out, int out_size) {
    const float* x     = (const float*)d_in[0];
    const float* Wqkv  = (const float*)d_in[1];
    const float* bqkv  = (const float*)d_in[2];
    const float* Wproj = (const float*)d_in[3];
    const float* bproj = (const float*)d_in[4];
    float* out = (float*)d_out;

    __half *qkvh, *atth, *xh, *wqkvh, *wprojh;
    cudaGetSymbolAddress((void**)&qkvh, g_qkvh);
    cudaGetSymbolAddress((void**)&atth, g_atth);
    cudaGetSymbolAddress((void**)&xh, g_xh);
    cudaGetSymbolAddress((void**)&wqkvh, g_wqkvh);
    cudaGetSymbolAddress((void**)&wprojh, g_wprojh);

    cudaFuncSetAttribute(attn_f16, cudaFuncAttributeMaxDynamicSharedMemorySize,
                         ATTN_SMEM_BYTES);
    cudaFuncSetAttribute(gemm_f16<true>, cudaFuncAttributeMaxDynamicSharedMemorySize,
                         GEMM_SMEM_BYTES);
    cudaFuncSetAttribute(gemm_f16<false>, cudaFuncAttributeMaxDynamicSharedMemorySize,
                         GEMM_SMEM_BYTES);

    // 0) Pre-convert inputs to fp16
    {
        int n4x = ROWS * DMODEL / 4;
        int n4q = DMODEL * QKV_N / 4;
        int n4p = DMODEL * DMODEL / 4;
        to_half<<<(n4x + 255) / 256, 256>>>(x, xh, n4x);
        to_half<<<(n4q + 255) / 256, 256>>>(Wqkv, wqkvh, n4q);
        to_half<<<(n4p + 255) / 256, 256>>>(Wproj, wprojh, n4p);
    }
    // 1) QKV GEMM -> fp16 qkv
    {
        dim3 grid(QKV_N / GBN, ROWS / GBM);
        gemm_f16<true><<<grid, 128, GEMM_SMEM_BYTES>>>(xh, wqkvh, bqkv, qkvh,
                                                       ROWS, QKV_N, DMODEL);
    }
    // 2) Causal attention (fp16 mma, intra-warp softmax) -> fp16
    {
        dim3 grid(SEQ / QT, NHEAD, BATCH);
        attn_f16<<<grid, 128, ATTN_SMEM_BYTES>>>(qkvh, atth);
    }
    // 3) Proj GEMM -> fp32 out
    {
        dim3 grid(DMODEL / GBN, ROWS / GBM);
        gemm_f16<false><<<grid, 128, GEMM_SMEM_BYTES>>>(atth, wprojh, bproj, out,
                                                        ROWS, DMODEL, DMODEL);
    }
}

// round 16
// speedup vs baseline: 2.4664x; 1.0257x over previous
#include <cuda_runtime.h>
#include <cuda_fp16.h>
#include <cstdint>
#include <math.h>
#include <math_constants.h>

typedef unsigned int u32;

// Problem constants
#define BATCH 2
#define SEQ   2048
#define DMODEL 2048
#define NHEAD 16
#define HDIM  128
#define ROWS  (BATCH * SEQ)          // 4096
#define QKV_N (3 * DMODEL)           // 6144

// Scratch (allocation-free rule: __device__ globals)
__device__ __half g_qkvh[(size_t)ROWS * QKV_N];      // fp16 QKV activations
__device__ __half g_atth[(size_t)ROWS * DMODEL];     // fp16 attention output
__device__ __half g_xh[(size_t)ROWS * DMODEL];       // fp16 x
__device__ __half g_wqkvh[(size_t)DMODEL * QKV_N];   // fp16 Wqkv
__device__ __half g_wprojh[(size_t)DMODEL * DMODEL]; // fp16 Wproj

// ---------------------------------------------------------------------------
// Helpers
// ---------------------------------------------------------------------------
__device__ __forceinline__ void cp_async16(u32 smem_addr, const void* gptr) {
    asm volatile("cp.async.cg.shared.global [%0], [%1], 16;\n"
                 :: "r"(smem_addr), "l"(gptr));
}
__device__ __forceinline__ void cp_commit() {
    asm volatile("cp.async.commit_group;\n" ::: "memory");
}
template <int N>
__device__ __forceinline__ void cp_wait() {
    asm volatile("cp.async.wait_group %0;\n" :: "n"(N) : "memory");
}

__device__ __forceinline__ void mma_f16(float* c, const u32* a, const u32* b) {
    asm volatile(
        "mma.sync.aligned.m16n8k16.row.col.f32.f16.f16.f32 "
        "{%0,%1,%2,%3}, {%4,%5,%6,%7}, {%8,%9}, {%0,%1,%2,%3};\n"
        : "+f"(c[0]), "+f"(c[1]), "+f"(c[2]), "+f"(c[3])
        : "r"(a[0]), "r"(a[1]), "r"(a[2]), "r"(a[3]), "r"(b[0]), "r"(b[1]));
}
__device__ __forceinline__ void ldsm_x4(u32* r, u32 addr) {
    asm volatile("ldmatrix.sync.aligned.m8n8.x4.shared.b16 {%0,%1,%2,%3}, [%4];"
                 : "=r"(r[0]), "=r"(r[1]), "=r"(r[2]), "=r"(r[3]) : "r"(addr));
}
__device__ __forceinline__ void ldsm_x4_t(u32* r, u32 addr) {
    asm volatile("ldmatrix.sync.aligned.m8n8.x4.trans.shared.b16 {%0,%1,%2,%3}, [%4];"
                 : "=r"(r[0]), "=r"(r[1]), "=r"(r[2]), "=r"(r[3]) : "r"(addr));
}

// ---------------------------------------------------------------------------
// Elementwise fp32 -> fp16 prepass
// ---------------------------------------------------------------------------
__global__ __launch_bounds__(256)
void to_half(const float* __restrict__ in, __half* __restrict__ out, int n4) {
    int i = blockIdx.x * 256 + threadIdx.x;
    if (i < n4) {
        float4 v = ((const float4*)in)[i];
        __half2* o = (__half2*)out;
        o[2 * i + 0] = __floats2half2_rn(v.x, v.y);
        o[2 * i + 1] = __floats2half2_rn(v.z, v.w);
    }
}

// ---------------------------------------------------------------------------
// FP16 tensor-core GEMM: C[M,N] = A[M,K] @ B[K,N] + bias[N]
// 128x128 tile, BK=32, 3-stage cp.async, 128 threads (4 warps, 64x64 warp
// tiles). SINGLE __syncthreads per k-tile: the top-of-iter barrier both
// publishes tile kt to all warps and orders tile kt+2's loads (same buffer
// as kt-1) after all warps finished computing kt-1.
// ---------------------------------------------------------------------------
#define GBM 128
#define GBN 128
#define GBK 32
#define HASTR 40
#define HBSTR 136
#define NSTAGE 3
#define A_TILE_H (GBM * HASTR)
#define B_TILE_H (GBK * HBSTR)
#define GEMM_SMEM_BYTES (NSTAGE * (A_TILE_H + B_TILE_H) * 2)   // 56832

template <bool HALF_OUT>
__global__ __launch_bounds__(128)
void gemm_f16(const __half* __restrict__ A, const __half* __restrict__ B,
              const float* __restrict__ bias, void* __restrict__ Cv,
              int M, int N, int K) {
    extern __shared__ __half smh[];
    __half* Asm = smh;
    __half* Bsm = smh + NSTAGE * A_TILE_H;

    const int tid = threadIdx.x;
    const int lane = tid & 31;
    const int wid  = tid >> 5;
    const int g = lane >> 2;
    const int t = lane & 3;
    const int warp_m = (wid & 1) * 64;
    const int warp_n = (wid >> 1) * 64;

    const int rowBase = blockIdx.y * GBM;
    const int colBase = blockIdx.x * GBN;

    u32 asbase = (u32)__cvta_generic_to_shared(Asm);
    u32 bsbase = (u32)__cvta_generic_to_shared(Bsm);

    const int aRow = (lane & 7) + ((lane >> 3) & 1) * 8;
    const int aCol = (lane >> 4) * 8;
    const int bRow = (lane & 7) + ((lane >> 3) & 1) * 8;
    const int bColD = (lane >> 4) * 8;

    float acc[4][8][4];
    #pragma unroll
    for (int i = 0; i < 4; i++)
        #pragma unroll
        for (int j = 0; j < 8; j++)
            #pragma unroll
            for (int v = 0; v < 4; v++) acc[i][j][v] = 0.0f;

    const int NT = K / GBK;

    // Prologue: tiles 0..NSTAGE-2, one commit-group each
    #pragma unroll
    for (int s = 0; s < NSTAGE - 1; s++) {
        const int k0g = s * GBK;
        u32 asd = asbase + (u32)s * (A_TILE_H * 2u);
        u32 bsd = bsbase + (u32)s * (B_TILE_H * 2u);
        #pragma unroll
        for (int it = 0; it < 4; it++) {
            int c = tid + it * 128;
            int ar = c >> 2, akc = (c & 3) * 8;
            cp_async16(asd + (u32)(ar * HASTR + akc) * 2u,
                       &A[(size_t)(rowBase + ar) * K + k0g + akc]);
            int br = c >> 4, bnc = (c & 15) * 8;
            cp_async16(bsd + (u32)(br * HBSTR + bnc) * 2u,
                       &B[(size_t)(k0g + br) * N + colBase + bnc]);
        }
        cp_commit();
    }

    for (int kt = 0; kt < NT; kt++) {
        cp_wait<NSTAGE - 2>();   // tile kt landed (<=1 group outstanding)
        __syncthreads();         // publish tile kt; all warps done with kt-1

        // Issue tile kt+2 into buffer (kt+2)%3 (== kt-1's buffer, now free)
        if (kt + NSTAGE - 1 < NT) {
            const int s = (kt + NSTAGE - 1) % NSTAGE;
            const int k0g = (kt + NSTAGE - 1) * GBK;
            u32 asd = asbase + (u32)s * (A_TILE_H * 2u);
            u32 bsd = bsbase + (u32)s * (B_TILE_H * 2u);
            #pragma unroll
            for (int it = 0; it < 4; it++) {
                int c = tid + it * 128;
                int ar = c >> 2, akc = (c & 3) * 8;
                cp_async16(asd + (u32)(ar * HASTR + akc) * 2u,
                           &A[(size_t)(rowBase + ar) * K + k0g + akc]);
                int br = c >> 4, bnc = (c & 15) * 8;
                cp_async16(bsd + (u32)(br * HBSTR + bnc) * 2u,
                           &B[(size_t)(k0g + br) * N + colBase + bnc]);
            }
        }
        cp_commit();             // uniform group count (may be empty)

        const int buf = kt % NSTAGE;
        const u32 asb = asbase + (u32)buf * (A_TILE_H * 2u);
        const u32 bsb = bsbase + (u32)buf * (B_TILE_H * 2u);

        #pragma unroll
        for (int ks = 0; ks < 2; ks++) {
            const int k0 = ks * 16;
            u32 af[4][4];
            #pragma unroll
            for (int mt = 0; mt < 4; mt++) {
                u32 addr = asb + (u32)((warp_m + mt * 16 + aRow) * HASTR
                                       + k0 + aCol) * 2u;
                ldsm_x4(af[mt], addr);
            }
            #pragma unroll
            for (int nbp = 0; nbp < 4; nbp++) {
                u32 r4[4];
                u32 addr = bsb + (u32)((k0 + bRow) * HBSTR
                                       + warp_n + nbp * 16 + bColD) * 2u;
                ldsm_x4_t(r4, addr);
                u32 b0[2] = { r4[0], r4[1] };
                u32 b1[2] = { r4[2], r4[3] };
                #pragma unroll
                for (int mt = 0; mt < 4; mt++) {
                    mma_f16(acc[mt][nbp * 2 + 0], af[mt], b0);
                    mma_f16(acc[mt][nbp * 2 + 1], af[mt], b1);
                }
            }
        }
    }

    #pragma unroll
    for (int mt = 0; mt < 4; mt++) {
        int row = rowBase + warp_m + mt * 16 + g;
        #pragma unroll
        for (int nt = 0; nt < 8; nt++) {
            int col = colBase + warp_n + nt * 8 + 2 * t;
            float b0 = bias[col], b1 = bias[col + 1];
            if (HALF_OUT) {
                __half* C = (__half*)Cv;
                *(__half2*)&C[(size_t)row * N + col] =
                    __floats2half2_rn(acc[mt][nt][0] + b0, acc[mt][nt][1] + b1);
                *(__half2*)&C[(size_t)(row + 8) * N + col] =
                    __floats2half2_rn(acc[mt][nt][2] + b0, acc[mt][nt][3] + b1);
            } else {
                float* C = (float*)Cv;
                *(float2*)&C[(size_t)row * N + col] =
                    make_float2(acc[mt][nt][0] + b0, acc[mt][nt][1] + b1);
                *(float2*)&C[(size_t)(row + 8) * N + col] =
                    make_float2(acc[mt][nt][2] + b0, acc[mt][nt][3] + b1);
            }
        }
    }
}

// ---------------------------------------------------------------------------
// Flash attention, fp16 ldsm+mma, intra-warp softmax (unchanged, Round 15)
// ---------------------------------------------------------------------------
#define QT 64
#define KSTR 136
#define SSTR 72
#define AQ_H (QT * KSTR)
#define AS_H (QT * SSTR)
#define ATTN_SMEM_BYTES ((3 * AQ_H + AS_H) * 2)    // 61440

__global__ __launch_bounds__(128)
void attn_f16(const __half* __restrict__ qkv, __half* __restrict__ out) {
    extern __shared__ __half smha[];
    __half* Qs = smha;
    __half* Ks = Qs + AQ_H;
    __half* Vs = Ks + AQ_H;
    __half* Ss = Vs + AQ_H;

    const int qt  = gridDim.x - 1 - blockIdx.x;
    const int h   = blockIdx.y;
    const int b   = blockIdx.z;
    const int tid = threadIdx.x;
    const int lane = tid & 31;
    const int w    = tid >> 5;
    const int g    = lane >> 2;
    const int t    = lane & 3;
    const int wm   = w * 16;

    const int aRow = (lane & 7) + ((lane >> 3) & 1) * 8;
    const int aCol = (lane >> 4) * 8;
    const int nRow = (lane & 7) + (lane >> 4) * 8;
    const int kCol = ((lane >> 3) & 1) * 8;
    const int bRow = (lane & 7) + ((lane >> 3) & 1) * 8;
    const int bColD = (lane >> 4) * 8;

    const u32 qs_u = (u32)__cvta_generic_to_shared(Qs);
    const u32 ks_u = (u32)__cvta_generic_to_shared(Ks);
    const u32 vs_u = (u32)__cvta_generic_to_shared(Vs);
    const u32 ss_u = (u32)__cvta_generic_to_shared(Ss);

    const float scale = 0.08838834764831845f;
    const size_t base = (size_t)b * SEQ * QKV_N;
    const int hoff = h * HDIM;

    for (int idx = tid; idx < QT * 16; idx += 128) {
        int r  = idx >> 4;
        int c8 = (idx & 15) * 8;
        *(float4*)&Qs[r * KSTR + c8] =
            *(const float4*)&qkv[base + (size_t)(qt * QT + r) * QKV_N + hoff + c8];
    }

    float m_run[2] = { -CUDART_INF_F, -CUDART_INF_F };
    float l_run[2] = { 0.0f, 0.0f };
    float O[16][4];
    #pragma unroll
    for (int dbl = 0; dbl < 16; dbl++)
        #pragma unroll
        for (int v = 0; v < 4; v++) O[dbl][v] = 0.0f;

    for (int kt = 0; kt <= qt; kt++) {
        __syncthreads();
        for (int idx = tid; idx < QT * 16; idx += 128) {
            int r  = idx >> 4;
            int c8 = (idx & 15) * 8;
            size_t rowoff = base + (size_t)(kt * QT + r) * QKV_N + hoff;
            *(float4*)&Ks[r * KSTR + c8] = *(const float4*)&qkv[rowoff + DMODEL + c8];
            *(float4*)&Vs[r * KSTR + c8] = *(const float4*)&qkv[rowoff + 2 * DMODEL + c8];
        }
        __syncthreads();

        float sa[8][4];
        #pragma unroll
        for (int nb = 0; nb < 8; nb++)
            #pragma unroll
            for (int v = 0; v < 4; v++) sa[nb][v] = 0.0f;

        #pragma unroll
        for (int ks = 0; ks < 8; ks++) {
            const int k0 = ks * 16;
            u32 A4[4];
            ldsm_x4(A4, qs_u + (u32)((wm + aRow) * KSTR + k0 + aCol) * 2u);
            #pragma unroll
            for (int nbp = 0; nbp < 4; nbp++) {
                u32 r4[4];
                ldsm_x4(r4, ks_u + (u32)((nbp * 16 + nRow) * KSTR
                                         + k0 + kCol) * 2u);
                u32 b0[2] = { r4[0], r4[1] };
                u32 b1[2] = { r4[2], r4[3] };
                mma_f16(sa[nbp * 2 + 0], A4, b0);
                mma_f16(sa[nbp * 2 + 1], A4, b1);
            }
        }

        #pragma unroll
        for (int nb = 0; nb < 8; nb++)
            #pragma unroll
            for (int v = 0; v < 4; v++) sa[nb][v] *= scale;
        if (kt == qt) {
            #pragma unroll
            for (int nb = 0; nb < 8; nb++) {
                const int c0 = nb * 8 + 2 * t;
                if (c0     > wm + g)     sa[nb][0] = -CUDART_INF_F;
                if (c0 + 1 > wm + g)     sa[nb][1] = -CUDART_INF_F;
                if (c0     > wm + 8 + g) sa[nb][2] = -CUDART_INF_F;
                if (c0 + 1 > wm + 8 + g) sa[nb][3] = -CUDART_INF_F;
            }
        }

        float tmax[2] = { -CUDART_INF_F, -CUDART_INF_F };
        #pragma unroll
        for (int nb = 0; nb < 8; nb++) {
            tmax[0] = fmaxf(tmax[0], fmaxf(sa[nb][0], sa[nb][1]));
            tmax[1] = fmaxf(tmax[1], fmaxf(sa[nb][2], sa[nb][3]));
        }
        #pragma unroll
        for (int i = 0; i < 2; i++) {
            tmax[i] = fmaxf(tmax[i], __shfl_xor_sync(0xffffffffu, tmax[i], 1));
            tmax[i] = fmaxf(tmax[i], __shfl_xor_sync(0xffffffffu, tmax[i], 2));
        }

        float fs[2];
        #pragma unroll
        for (int i = 0; i < 2; i++) {
            float mn = fmaxf(m_run[i], tmax[i]);
            fs[i] = __expf(m_run[i] - mn);
            m_run[i] = mn;
        }

        float tsum[2] = { 0.0f, 0.0f };
        #pragma unroll
        for (int nb = 0; nb < 8; nb++) {
            float p0 = __expf(sa[nb][0] - m_run[0]);
            float p1 = __expf(sa[nb][1] - m_run[0]);
            float p2 = __expf(sa[nb][2] - m_run[1]);
            float p3 = __expf(sa[nb][3] - m_run[1]);
            tsum[0] += p0 + p1;
            tsum[1] += p2 + p3;
            const int col = nb * 8 + 2 * t;
            *(__half2*)&Ss[(wm + g) * SSTR + col]     = __floats2half2_rn(p0, p1);
            *(__half2*)&Ss[(wm + 8 + g) * SSTR + col] = __floats2half2_rn(p2, p3);
        }
        #pragma unroll
        for (int i = 0; i < 2; i++) {
            tsum[i] += __shfl_xor_sync(0xffffffffu, tsum[i], 1);
            tsum[i] += __shfl_xor_sync(0xffffffffu, tsum[i], 2);
            l_run[i] = l_run[i] * fs[i] + tsum[i];
        }
        __syncwarp();

        #pragma unroll
        for (int dbl = 0; dbl < 16; dbl++) {
            O[dbl][0] *= fs[0];
            O[dbl][1] *= fs[0];
            O[dbl][2] *= fs[1];
            O[dbl][3] *= fs[1];
        }
        #pragma unroll
        for (int ks = 0; ks < 4; ks++) {
            const int k0 = ks * 16;
            u32 A4[4];
            ldsm_x4(A4, ss_u + (u32)((wm + aRow) * SSTR + k0 + aCol) * 2u);
            #pragma unroll
            for (int nbp = 0; nbp < 8; nbp++) {
                u32 r4[4];
                ldsm_x4_t(r4, vs_u + (u32)((k0 + bRow) * KSTR
                                           + nbp * 16 + bColD) * 2u);
                u32 b0[2] = { r4[0], r4[1] };
                u32 b1[2] = { r4[2], r4[3] };
                mma_f16(O[nbp * 2 + 0], A4, b0);
                mma_f16(O[nbp * 2 + 1], A4, b1);
            }
        }
    }

    float inv0 = 1.0f / l_run[0];
    float inv1 = 1.0f / l_run[1];
    const size_t obase = ((size_t)b * SEQ + (size_t)qt * QT) * DMODEL + hoff;
    #pragma unroll
    for (int dbl = 0; dbl < 16; dbl++) {
        const int col = dbl * 8 + 2 * t;
        *(__half2*)&out[obase + (size_t)(wm + g) * DMODEL + col] =
            __floats2half2_rn(O[dbl][0] * inv0, O[dbl][1] * inv0);
        *(__half2*)&out[obase + (size_t)(wm + 8 + g) * DMODEL + col] =
            __floats2half2_rn(O[dbl][2] * inv1, O[dbl][3] * inv1);
    }
}

// ---------------------------------------------------------------------------
// Launch
// ---------------------------------------------------------------------------
extern "C" void kernel_launch(void* const* d_in, const int* in_sizes, int n_in,
                              void* d_out, int out_size) {
    const float* x     = (const float*)d_in[0];
    const float* Wqkv  = (const float*)d_in[1];
    const float* bqkv  = (const float*)d_in[2];
    const float* Wproj = (const float*)d_in[3];
    const float* bproj = (const float*)d_in[4];
    float* out = (float*)d_out;

    __half *qkvh, *atth, *xh, *wqkvh, *wprojh;
    cudaGetSymbolAddress((void**)&qkvh, g_qkvh);
    cudaGetSymbolAddress((void**)&atth, g_atth);
    cudaGetSymbolAddress((void**)&xh, g_xh);
    cudaGetSymbolAddress((void**)&wqkvh, g_wqkvh);
    cudaGetSymbolAddress((void**)&wprojh, g_wprojh);

    cudaFuncSetAttribute(attn_f16, cudaFuncAttributeMaxDynamicSharedMemorySize,
                         ATTN_SMEM_BYTES);
    cudaFuncSetAttribute(gemm_f16<true>, cudaFuncAttributeMaxDynamicSharedMemorySize,
                         GEMM_SMEM_BYTES);
    cudaFuncSetAttribute(gemm_f16<false>, cudaFuncAttributeMaxDynamicSharedMemorySize,
                         GEMM_SMEM_BYTES);

    // 0) Pre-convert inputs to fp16
    {
        int n4x = ROWS * DMODEL / 4;
        int n4q = DMODEL * QKV_N / 4;
        int n4p = DMODEL * DMODEL / 4;
        to_half<<<(n4x + 255) / 256, 256>>>(x, xh, n4x);
        to_half<<<(n4q + 255) / 256, 256>>>(Wqkv, wqkvh, n4q);
        to_half<<<(n4p + 255) / 256, 256>>>(Wproj, wprojh, n4p);
    }
    // 1) QKV GEMM -> fp16 qkv
    {
        dim3 grid(QKV_N / GBN, ROWS / GBM);
        gemm_f16<true><<<grid, 128, GEMM_SMEM_BYTES>>>(xh, wqkvh, bqkv, qkvh,
                                                       ROWS, QKV_N, DMODEL);
    }
    // 2) Causal attention (fp16 mma, intra-warp softmax) -> fp16
    {
        dim3 grid(SEQ / QT, NHEAD, BATCH);
        attn_f16<<<grid, 128, ATTN_SMEM_BYTES>>>(qkvh, atth);
    }
    // 3) Proj GEMM -> fp32 out
    {
        dim3 grid(DMODEL / GBN, ROWS / GBM);
        gemm_f16<false><<<grid, 128, GEMM_SMEM_BYTES>>>(atth, wprojh, bproj, out,
                                                        ROWS, DMODEL, DMODEL);
    }
}